// round 14
// baseline (speedup 1.0000x reference)
#include <cuda_runtime.h>
#include <cuda_bf16.h>
#include <math.h>
#include <stdint.h>

#define BATCH 2
#define SEQ   2048
#define EMB   1024
#define HEADS 16
#define DHEAD 64
#define MROWS (BATCH*SEQ)         // 4096
#define NSLICE (BATCH*HEADS)      // 32

// ---------------- scratch (static device globals; no allocation) -------------
__device__ __nv_bfloat16 g_xh [MROWS*EMB], g_xl [MROWS*EMB];
__device__ __nv_bfloat16 g_txh[MROWS*EMB], g_txl[MROWS*EMB];
__device__ __nv_bfloat16 g_Kh [MROWS*EMB], g_Kl [MROWS*EMB];
__device__ __nv_bfloat16 g_TQh[MROWS*EMB], g_TQl[MROWS*EMB];
__device__ __nv_bfloat16 g_Vth[NSLICE*DHEAD*SEQ], g_Vtl[NSLICE*DHEAD*SEQ];
__device__ __nv_bfloat16 g_Oh [MROWS*EMB], g_Ol [MROWS*EMB];
__device__ __nv_bfloat16 g_Wkh [EMB*EMB], g_Wkl [EMB*EMB];
__device__ __nv_bfloat16 g_Wvh [EMB*EMB], g_Wvl [EMB*EMB];
__device__ __nv_bfloat16 g_Wtqh[EMB*EMB], g_Wtql[EMB*EMB];
__device__ __nv_bfloat16 g_Wouth[EMB*EMB], g_Woutl[EMB*EMB];

// ---------------- small helpers ----------------------------------------------
__device__ __forceinline__ uint32_t smem_u32(const void* p) {
    uint32_t a;
    asm("{ .reg .u64 t; cvta.to.shared.u64 t, %1; cvt.u32.u64 %0, t; }" : "=r"(a) : "l"(p));
    return a;
}
#define CP_ASYNC16(dst, src) \
    asm volatile("cp.async.cg.shared.global [%0], [%1], 16;" :: "r"(dst), "l"(src) : "memory")
#define CP_COMMIT() asm volatile("cp.async.commit_group;" ::: "memory")
#define CP_WAIT2()  asm volatile("cp.async.wait_group 2;" ::: "memory")
#define CP_WAIT1()  asm volatile("cp.async.wait_group 1;" ::: "memory")
#define CP_WAIT0()  asm volatile("cp.async.wait_group 0;" ::: "memory")

__device__ __forceinline__ void ldsm_x4(uint32_t r[4], uint32_t addr) {
    asm volatile("ldmatrix.sync.aligned.m8n8.x4.shared.b16 {%0,%1,%2,%3}, [%4];"
                 : "=r"(r[0]), "=r"(r[1]), "=r"(r[2]), "=r"(r[3]) : "r"(addr));
}
__device__ __forceinline__ void mma16816(float c[4], const uint32_t a[4],
                                         uint32_t b0, uint32_t b1) {
    asm volatile("mma.sync.aligned.m16n8k16.row.col.f32.bf16.bf16.f32 "
                 "{%0,%1,%2,%3},{%4,%5,%6,%7},{%8,%9},{%0,%1,%2,%3};"
                 : "+f"(c[0]), "+f"(c[1]), "+f"(c[2]), "+f"(c[3])
                 : "r"(a[0]), "r"(a[1]), "r"(a[2]), "r"(a[3]), "r"(b0), "r"(b1));
}
__device__ __forceinline__ uint32_t pack2(__nv_bfloat16 a, __nv_bfloat16 b) {
    return (uint32_t)__bfloat16_as_ushort(a) | ((uint32_t)__bfloat16_as_ushort(b) << 16);
}
__device__ __forceinline__ void split2(float x, __nv_bfloat16& h, __nv_bfloat16& l) {
    h = __float2bfloat16(x);
    l = __float2bfloat16(x - __bfloat162float(h));
}
__device__ __forceinline__ float ex2f(float x) {
    float r;
    asm("ex2.approx.ftz.f32 %0, %1;" : "=f"(r) : "f"(x));
    return r;
}

// smem tile geometry
#define SSTR16 48            // 16-half rows (GEMM BK=16), conflict-free (r*12 mod 32)
#define TB16   (128*SSTR16)  // 6144 (one 128x16 operand tile)
#define SSTR64 144           // 64-half rows (flash kernel), conflict-free
#define TILE_B (64*SSTR64)   // 9216

// 128 rows x 16 halves (32 B data per row)
__device__ __forceinline__ void fill_rows16(uint32_t dst, const __nv_bfloat16* src,
                                            int ld, int tid) {
    for (int j = tid; j < 128 * 2; j += 256) {
        int r = j >> 1, c = j & 1;
        CP_ASYNC16(dst + r * SSTR16 + c * 16, src + (size_t)r * ld + c * 8);
    }
}

// ---------------- prep: convert x/tx/Wout + permute/split Wqkv,Wtqkv ---------
#define NQ ((MROWS*EMB)/4)       // 1048576
#define WQ ((EMB*EMB)/4)         // 262144
#define CONVQ (2*NQ + WQ)        // 2359296
#define PERMN (EMB*EMB)          // 1048576

__global__ void prep_kernel(const float* __restrict__ X0, const float* __restrict__ X1,
                            const float* __restrict__ X2,
                            const float* __restrict__ Wqkv, const float* __restrict__ Wtqkv)
{
    int i = blockIdx.x * blockDim.x + threadIdx.x;
    if (i < CONVQ) {
        const float* X; __nv_bfloat16 *H, *L;
        if (i < NQ)          { X = X0; H = g_xh;  L = g_xl; }
        else if (i < 2 * NQ) { X = X1; H = g_txh; L = g_txl; i -= NQ; }
        else                 { X = X2; H = g_Wouth; L = g_Woutl; i -= 2 * NQ; }
        float4 v = ((const float4*)X)[i];
        __nv_bfloat16 h0, h1, h2, h3, l0, l1, l2, l3;
        split2(v.x, h0, l0); split2(v.y, h1, l1);
        split2(v.z, h2, l2); split2(v.w, h3, l3);
        ((uint2*)H)[i] = make_uint2(pack2(h0, h1), pack2(h2, h3));
        ((uint2*)L)[i] = make_uint2(pack2(l0, l1), pack2(l2, l3));
        return;
    }
    i -= CONVQ;
    if (i >= PERMN) return;
    int k = i & 1023, n = i >> 10;
    int h = n >> 6, d = n & 63;
    size_t dst = (size_t)n * EMB + k;
    float vk  = Wqkv [(size_t)(d * 48 + 16 + h) * EMB + k];
    float vv  = Wqkv [(size_t)(d * 48 + 32 + h) * EMB + k];
    float vtq = Wtqkv[(size_t)(d * 48 +  0 + h) * EMB + k];
    __nv_bfloat16 hh, ll;
    split2(vk,  hh, ll); g_Wkh [dst] = hh; g_Wkl [dst] = ll;
    split2(vv,  hh, ll); g_Wvh [dst] = hh; g_Wvl [dst] = ll;
    split2(vtq, hh, ll); g_Wtqh[dst] = hh; g_Wtql[dst] = ll;
}

// ---------------- GEMM core: fused 3-term, BK=16, 4 stages (occ 2) -----------
// stage layout: [Ah | Al | Bh | Bl], each 128 rows x 16 halves (6144 B)
#define KCH16 64
#define STG16 (4*TB16)      // 24576
#define GSMEM 98304         // 4*STG16; >= 66048 transpose tile

__device__ __forceinline__ void fill_all16(uint32_t st,
    const __nv_bfloat16* Ah, const __nv_bfloat16* Al,
    const __nv_bfloat16* Bh, const __nv_bfloat16* Bl,
    int rowBase, int colBase, int k0, int tid)
{
    fill_rows16(st,           Ah + (size_t)rowBase * EMB + k0, EMB, tid);
    fill_rows16(st + TB16,    Al + (size_t)rowBase * EMB + k0, EMB, tid);
    fill_rows16(st + 2*TB16,  Bh + (size_t)colBase * EMB + k0, EMB, tid);
    fill_rows16(st + 3*TB16,  Bl + (size_t)colBase * EMB + k0, EMB, tid);
}

// all 3 split terms over one BK=16 stage; each fragment loaded once, term-major
__device__ __forceinline__ void compute_all16(uint32_t st, int wrow, int wcol,
                                              int lane, float (*cfr)[4])
{
    const int arow  = wrow + (lane & 15);
    const int acolB = (lane >> 4) * 16;             // byte offset within 32B row
    const int brow  = wcol + (lane & 7) + ((lane >> 4) << 3);
    const int bcolB = ((lane >> 3) & 1) * 16;
    uint32_t ah[4][4], al[4][4], bh[2][4], bl[2][4];
#pragma unroll
    for (int mt = 0; mt < 4; mt++) {
        uint32_t off = (uint32_t)(arow + mt * 16) * SSTR16 + acolB;
        ldsm_x4(ah[mt], st + off);
        ldsm_x4(al[mt], st + TB16 + off);
    }
#pragma unroll
    for (int np = 0; np < 2; np++) {
        uint32_t off = (uint32_t)(brow + np * 16) * SSTR16 + bcolB;
        ldsm_x4(bh[np], st + 2 * TB16 + off);
        ldsm_x4(bl[np], st + 3 * TB16 + off);
    }
#pragma unroll
    for (int mt = 0; mt < 4; mt++)
#pragma unroll
        for (int np = 0; np < 2; np++) {
            mma16816(cfr[(mt * 2 + np) * 2 + 0], ah[mt], bh[np][0], bh[np][1]);
            mma16816(cfr[(mt * 2 + np) * 2 + 1], ah[mt], bh[np][2], bh[np][3]);
        }
#pragma unroll
    for (int mt = 0; mt < 4; mt++)
#pragma unroll
        for (int np = 0; np < 2; np++) {
            mma16816(cfr[(mt * 2 + np) * 2 + 0], al[mt], bh[np][0], bh[np][1]);
            mma16816(cfr[(mt * 2 + np) * 2 + 1], al[mt], bh[np][2], bh[np][3]);
        }
#pragma unroll
    for (int mt = 0; mt < 4; mt++)
#pragma unroll
        for (int np = 0; np < 2; np++) {
            mma16816(cfr[(mt * 2 + np) * 2 + 0], ah[mt], bl[np][0], bl[np][1]);
            mma16816(cfr[(mt * 2 + np) * 2 + 1], ah[mt], bl[np][2], bl[np][3]);
        }
}

__device__ __forceinline__ void gemm_core(
    const __nv_bfloat16* Ah, const __nv_bfloat16* Al,
    const __nv_bfloat16* Bh, const __nv_bfloat16* Bl,
    int rowBase, int colBase, uint32_t sb, int tid, int lane,
    int wrow, int wcol, float (*cfr)[4])
{
    fill_all16(sb,             Ah, Al, Bh, Bl, rowBase, colBase, 0,  tid); CP_COMMIT();
    fill_all16(sb + STG16,     Ah, Al, Bh, Bl, rowBase, colBase, 16, tid); CP_COMMIT();
    fill_all16(sb + 2 * STG16, Ah, Al, Bh, Bl, rowBase, colBase, 32, tid); CP_COMMIT();
    for (int c = 0; c < KCH16; c++) {
        if (c + 2 < KCH16)      { CP_WAIT2(); }
        else if (c + 1 < KCH16) { CP_WAIT1(); }
        else                    { CP_WAIT0(); }
        __syncthreads();
        if (c + 3 < KCH16) {
            fill_all16(sb + ((c + 3) & 3) * STG16, Ah, Al, Bh, Bl,
                       rowBase, colBase, (c + 3) << 4, tid);
            CP_COMMIT();
        }
        compute_all16(sb + (c & 3) * STG16, wrow, wcol, lane, cfr);
    }
    __syncthreads();
}

// ---------------- merged projection GEMM (z: 0=K split, 1=V->Vt, 2=TQ split) -
__global__ void __launch_bounds__(256, 2)
gemm_proj3()
{
    extern __shared__ char smem[];
    uint32_t sb = smem_u32(smem);
    const int tid = threadIdx.x, lane = tid & 31, warp = tid >> 5;
    const int rowBase = blockIdx.y * 128, colBase = blockIdx.x * 128;
    const int z = blockIdx.z;
    const int wrow = (warp >> 2) * 64, wcol = (warp & 3) * 32;

    const __nv_bfloat16 *Ah, *Al, *Bh, *Bl;
    if (z == 0)      { Ah = g_xh;  Al = g_xl;  Bh = g_Wkh;  Bl = g_Wkl;  }
    else if (z == 1) { Ah = g_xh;  Al = g_xl;  Bh = g_Wvh;  Bl = g_Wvl;  }
    else             { Ah = g_txh; Al = g_txl; Bh = g_Wtqh; Bl = g_Wtql; }

    float cfr[16][4];
#pragma unroll
    for (int i = 0; i < 16; i++)
#pragma unroll
        for (int j = 0; j < 4; j++) cfr[i][j] = 0.f;

    gemm_core(Ah, Al, Bh, Bl, rowBase, colBase, sb, tid, lane, wrow, wcol, cfr);

    if (z != 1) {
        __nv_bfloat16* H = (z == 0) ? g_Kh : g_TQh;
        __nv_bfloat16* L = (z == 0) ? g_Kl : g_TQl;
#pragma unroll
        for (int mt = 0; mt < 4; mt++)
#pragma unroll
            for (int np = 0; np < 2; np++)
#pragma unroll
                for (int t8 = 0; t8 < 2; t8++) {
                    int nt = np * 2 + t8;
                    int row = rowBase + wrow + mt * 16 + (lane >> 2);
                    int col = colBase + wcol + nt * 8 + 2 * (lane & 3);
                    float* cc = cfr[(mt * 2 + np) * 2 + t8];
#pragma unroll
                    for (int half = 0; half < 2; half++) {
                        int r = row + half * 8;
                        __nv_bfloat16 h0, h1, l0, l1;
                        split2(cc[half * 2], h0, l0); split2(cc[half * 2 + 1], h1, l1);
                        *(uint32_t*)(H + (size_t)r * EMB + col) = pack2(h0, h1);
                        *(uint32_t*)(L + (size_t)r * EMB + col) = pack2(l0, l1);
                    }
                }
    } else {
        // V: transpose in smem, write Vt[z][d][t] split bf16, t-coalesced
        float* tile = (float*)smem;   // [col][row], pitch 129: 66048 B <= 98304
#pragma unroll
        for (int mt = 0; mt < 4; mt++)
#pragma unroll
            for (int np = 0; np < 2; np++)
#pragma unroll
                for (int t8 = 0; t8 < 2; t8++) {
                    int nt = np * 2 + t8;
                    int rl = wrow + mt * 16 + (lane >> 2);
                    int cl = wcol + nt * 8 + 2 * (lane & 3);
                    float* cc = cfr[(mt * 2 + np) * 2 + t8];
#pragma unroll
                    for (int half = 0; half < 2; half++) {
                        tile[(cl + 0) * 129 + rl + half * 8] = cc[half * 2];
                        tile[(cl + 1) * 129 + rl + half * 8] = cc[half * 2 + 1];
                    }
                }
        __syncthreads();
        const int bb = rowBase >> 11, t0 = rowBase & 2047;
        for (int j = tid; j < 128 * 16; j += 256) {
            int c = j >> 4, tc = j & 15;
            int dg = colBase + c, hh = dg >> 6, dd = dg & 63;
            size_t dst = (((size_t)(bb * 16 + hh)) * DHEAD + dd) * SEQ + t0 + tc * 8;
            uint32_t hv[4], lv[4];
#pragma unroll
            for (int u = 0; u < 4; u++) {
                float v0 = tile[c * 129 + tc * 8 + 2 * u];
                float v1 = tile[c * 129 + tc * 8 + 2 * u + 1];
                __nv_bfloat16 h0, l0, h1, l1;
                split2(v0, h0, l0); split2(v1, h1, l1);
                hv[u] = pack2(h0, h1); lv[u] = pack2(l0, l1);
            }
            *(uint4*)(g_Vth + dst) = make_uint4(hv[0], hv[1], hv[2], hv[3]);
            *(uint4*)(g_Vtl + dst) = make_uint4(lv[0], lv[1], lv[2], lv[3]);
        }
    }
}

// ---------------- output GEMM (fp32 out) -------------------------------------
__global__ void __launch_bounds__(256, 2)
gemm_out(float* __restrict__ C)
{
    extern __shared__ char smem[];
    uint32_t sb = smem_u32(smem);
    const int tid = threadIdx.x, lane = tid & 31, warp = tid >> 5;
    const int rowBase = blockIdx.y * 128, colBase = blockIdx.x * 128;
    const int wrow = (warp >> 2) * 64, wcol = (warp & 3) * 32;

    float cfr[16][4];
#pragma unroll
    for (int i = 0; i < 16; i++)
#pragma unroll
        for (int j = 0; j < 4; j++) cfr[i][j] = 0.f;

    gemm_core(g_Oh, g_Ol, g_Wouth, g_Woutl, rowBase, colBase, sb, tid, lane, wrow, wcol, cfr);

#pragma unroll
    for (int mt = 0; mt < 4; mt++)
#pragma unroll
        for (int np = 0; np < 2; np++)
#pragma unroll
            for (int t8 = 0; t8 < 2; t8++) {
                int nt = np * 2 + t8;
                int row = rowBase + wrow + mt * 16 + (lane >> 2);
                int col = colBase + wcol + nt * 8 + 2 * (lane & 3);
                float* cc = cfr[(mt * 2 + np) * 2 + t8];
#pragma unroll
                for (int half = 0; half < 2; half++) {
                    int r = row + half * 8;
                    *(float2*)(C + (size_t)r * EMB + col) =
                        make_float2(cc[half * 2], cc[half * 2 + 1]);
                }
            }
}

// ---------------- fused flash attention (HMMA, 3-term split, 3-stage) --------
#define FSTAGE (4*TILE_B)    // 36864
#define FSMEM  (3*FSTAGE)    // 110592
#define NT     (SEQ/64)      // 32
#define SCALE2 11.5415603271862624f   // 8 * log2(e)

__device__ __forceinline__ void fill_kv(uint32_t st, int t, int b, int h, int z, int tid)
{
    const size_t koff = (size_t)(b * SEQ + t * 64) * EMB + h * DHEAD;
    const size_t voff = (size_t)z * DHEAD * SEQ + t * 64;
    for (int j = tid; j < 64 * 8; j += 256) {
        int r = j >> 3, c = j & 7;
        uint32_t d = (uint32_t)r * SSTR64 + c * 16;
        size_t ko = koff + (size_t)r * EMB + c * 8;
        size_t vo = voff + (size_t)r * SEQ + c * 8;
        CP_ASYNC16(st + d,              g_Kh  + ko);
        CP_ASYNC16(st + TILE_B + d,     g_Kl  + ko);
        CP_ASYNC16(st + 2 * TILE_B + d, g_Vth + vo);
        CP_ASYNC16(st + 3 * TILE_B + d, g_Vtl + vo);
    }
}

__device__ __forceinline__ void mma_pass(uint32_t bbase, const uint32_t A[4][4],
                                         float (*s)[4], int lane)
{
    const int brow  = (lane & 7) + ((lane >> 4) << 3);
    const int bcolh = ((lane >> 3) & 1) * 8;
#pragma unroll
    for (int ks = 0; ks < 4; ks++) {
#pragma unroll
        for (int pr = 0; pr < 4; pr++) {
            uint32_t bf[4];
            ldsm_x4(bf, bbase + (uint32_t)(brow + pr * 16) * SSTR64 + (bcolh + ks * 16) * 2);
            mma16816(s[pr * 2 + 0], A[ks], bf[0], bf[1]);
            mma16816(s[pr * 2 + 1], A[ks], bf[2], bf[3]);
        }
    }
}

__device__ __forceinline__ void mma_pass2(uint32_t bbase, const uint32_t A1[4][4],
                                          const uint32_t A2[4][4],
                                          float (*s)[4], int lane)
{
    const int brow  = (lane & 7) + ((lane >> 4) << 3);
    const int bcolh = ((lane >> 3) & 1) * 8;
#pragma unroll
    for (int ks = 0; ks < 4; ks++) {
#pragma unroll
        for (int pr = 0; pr < 4; pr++) {
            uint32_t bf[4];
            ldsm_x4(bf, bbase + (uint32_t)(brow + pr * 16) * SSTR64 + (bcolh + ks * 16) * 2);
            mma16816(s[pr * 2 + 0], A1[ks], bf[0], bf[1]);
            mma16816(s[pr * 2 + 1], A1[ks], bf[2], bf[3]);
            mma16816(s[pr * 2 + 0], A2[ks], bf[0], bf[1]);
            mma16816(s[pr * 2 + 1], A2[ks], bf[2], bf[3]);
        }
    }
}

__device__ __forceinline__ void pv2_pass(uint32_t bbase, const float (*s)[4],
                                         float (*o)[4], int lane)
{
    const int brow  = (lane & 7) + ((lane >> 4) << 3);
    const int bcolh = ((lane >> 3) & 1) * 8;
#pragma unroll
    for (int ks = 0; ks < 4; ks++) {
        const float* c0 = s[2 * ks];
        const float* c1 = s[2 * ks + 1];
        uint32_t Ah[4], Al[4];
        {
            __nv_bfloat16 hA, lA, hB, lB;
            split2(c0[0], hA, lA); split2(c0[1], hB, lB);
            Ah[0] = pack2(hA, hB); Al[0] = pack2(lA, lB);
            split2(c0[2], hA, lA); split2(c0[3], hB, lB);
            Ah[1] = pack2(hA, hB); Al[1] = pack2(lA, lB);
            split2(c1[0], hA, lA); split2(c1[1], hB, lB);
            Ah[2] = pack2(hA, hB); Al[2] = pack2(lA, lB);
            split2(c1[2], hA, lA); split2(c1[3], hB, lB);
            Ah[3] = pack2(hA, hB); Al[3] = pack2(lA, lB);
        }
#pragma unroll
        for (int pr = 0; pr < 4; pr++) {
            uint32_t bf[4];
            ldsm_x4(bf, bbase + (uint32_t)(brow + pr * 16) * SSTR64 + (bcolh + ks * 16) * 2);
            mma16816(o[pr * 2 + 0], Ah, bf[0], bf[1]);
            mma16816(o[pr * 2 + 1], Ah, bf[2], bf[3]);
            mma16816(o[pr * 2 + 0], Al, bf[0], bf[1]);
            mma16816(o[pr * 2 + 1], Al, bf[2], bf[3]);
        }
    }
}

__device__ __forceinline__ void pv_hi_pass(uint32_t bbase, const float (*s)[4],
                                           float (*o)[4], int lane)
{
    const int brow  = (lane & 7) + ((lane >> 4) << 3);
    const int bcolh = ((lane >> 3) & 1) * 8;
#pragma unroll
    for (int ks = 0; ks < 4; ks++) {
        const float* c0 = s[2 * ks];
        const float* c1 = s[2 * ks + 1];
        uint32_t Ah[4];
        Ah[0] = pack2(__float2bfloat16(c0[0]), __float2bfloat16(c0[1]));
        Ah[1] = pack2(__float2bfloat16(c0[2]), __float2bfloat16(c0[3]));
        Ah[2] = pack2(__float2bfloat16(c1[0]), __float2bfloat16(c1[1]));
        Ah[3] = pack2(__float2bfloat16(c1[2]), __float2bfloat16(c1[3]));
#pragma unroll
        for (int pr = 0; pr < 4; pr++) {
            uint32_t bf[4];
            ldsm_x4(bf, bbase + (uint32_t)(brow + pr * 16) * SSTR64 + (bcolh + ks * 16) * 2);
            mma16816(o[pr * 2 + 0], Ah, bf[0], bf[1]);
            mma16816(o[pr * 2 + 1], Ah, bf[2], bf[3]);
        }
    }
}

__global__ void __launch_bounds__(256, 2)
flash_attn()
{
    extern __shared__ char smem[];
    uint32_t sb = smem_u32(smem);
    const int tid = threadIdx.x, lane = tid & 31, warp = tid >> 5;
    const int rowBase = blockIdx.x * 128;
    const int z = blockIdx.y, b = z >> 4, h = z & 15;
    const int wrow = warp * 16;
    const int arow  = wrow + (lane & 15);
    const int acolh = (lane >> 4) * 8;

    // stage TQ (hi into stage0 low half, lo into stage0 high half)
    {
        const size_t toff = (size_t)(b * SEQ + rowBase) * EMB + h * DHEAD;
        for (int j = tid; j < 128 * 8; j += 256) {
            int r = j >> 3, c = j & 7;
            uint32_t d = (uint32_t)r * SSTR64 + c * 16;
            size_t go = toff + (size_t)r * EMB + c * 8;
            CP_ASYNC16(sb + d,         g_TQh + go);
            CP_ASYNC16(sb + 18432 + d, g_TQl + go);
        }
        CP_COMMIT(); CP_WAIT0();
    }
    __syncthreads();

    uint32_t aqh[4][4], aql[4][4];
#pragma unroll
    for (int ks = 0; ks < 4; ks++) {
        ldsm_x4(aqh[ks], sb + (uint32_t)arow * SSTR64 + (acolh + ks * 16) * 2);
        ldsm_x4(aql[ks], sb + 18432 + (uint32_t)arow * SSTR64 + (acolh + ks * 16) * 2);
    }
    __syncthreads();   // stage0 free for K/V

    float o[8][4];
#pragma unroll
    for (int i = 0; i < 8; i++)
#pragma unroll
        for (int j = 0; j < 4; j++) o[i][j] = 0.f;
    float m0 = -INFINITY, m1 = -INFINITY, l0 = 0.f, l1 = 0.f;

    fill_kv(sb, 0, b, h, z, tid);           CP_COMMIT();
    fill_kv(sb + FSTAGE, 1, b, h, z, tid);  CP_COMMIT();

    uint32_t stv[3] = {sb, sb + FSTAGE, sb + 2 * FSTAGE};
    for (int t = 0; t < NT; t++) {
        if (t + 1 < NT) { CP_WAIT1(); } else { CP_WAIT0(); }
        __syncthreads();   // all warps done with stage (t-1)%3 before refill
        if (t + 2 < NT) {
            fill_kv(stv[(t + 2) % 3], t + 2, b, h, z, tid);
            CP_COMMIT();
        }
        uint32_t st = stv[t % 3];

        float s[8][4];
#pragma unroll
        for (int i = 0; i < 8; i++)
#pragma unroll
            for (int j = 0; j < 4; j++) s[i][j] = 0.f;
        mma_pass2(st, aqh, aql, s, lane);      // (TQh + TQl) . Kh, Kh loaded once
        mma_pass(st + TILE_B, aqh, s, lane);   // TQh . Kl

        // online softmax in exp2 domain (scores scaled by 8*log2 e)
        float rm0 = -INFINITY, rm1 = -INFINITY;
#pragma unroll
        for (int i = 0; i < 8; i++) {
            s[i][0] *= SCALE2; s[i][1] *= SCALE2; s[i][2] *= SCALE2; s[i][3] *= SCALE2;
            rm0 = fmaxf(rm0, fmaxf(s[i][0], s[i][1]));
            rm1 = fmaxf(rm1, fmaxf(s[i][2], s[i][3]));
        }
        rm0 = fmaxf(rm0, __shfl_xor_sync(0xffffffffu, rm0, 1));
        rm0 = fmaxf(rm0, __shfl_xor_sync(0xffffffffu, rm0, 2));
        rm1 = fmaxf(rm1, __shfl_xor_sync(0xffffffffu, rm1, 1));
        rm1 = fmaxf(rm1, __shfl_xor_sync(0xffffffffu, rm1, 2));
        float mn0 = fmaxf(m0, rm0), mn1 = fmaxf(m1, rm1);
        float c0 = ex2f(m0 - mn0), c1 = ex2f(m1 - mn1);
        l0 *= c0; l1 *= c1;
#pragma unroll
        for (int i = 0; i < 8; i++) {
            o[i][0] *= c0; o[i][1] *= c0; o[i][2] *= c1; o[i][3] *= c1;
            float p0 = ex2f(s[i][0] - mn0), p1 = ex2f(s[i][1] - mn0);
            float p2 = ex2f(s[i][2] - mn1), p3 = ex2f(s[i][3] - mn1);
            s[i][0] = p0; s[i][1] = p1; s[i][2] = p2; s[i][3] = p3;
            l0 += p0 + p1; l1 += p2 + p3;
        }
        m0 = mn0; m1 = mn1;

        pv2_pass(st + 2 * TILE_B, s, o, lane);    // (Ph + Pl) . Vh, Vh loaded once
        pv_hi_pass(st + 3 * TILE_B, s, o, lane);  // Ph . Vl
        // no trailing sync: next iteration's top barrier guards stage reuse
    }

    l0 += __shfl_xor_sync(0xffffffffu, l0, 1);
    l0 += __shfl_xor_sync(0xffffffffu, l0, 2);
    l1 += __shfl_xor_sync(0xffffffffu, l1, 1);
    l1 += __shfl_xor_sync(0xffffffffu, l1, 2);
    float inv0 = 1.f / l0, inv1 = 1.f / l1;

    const int row0 = rowBase + wrow + (lane >> 2);
#pragma unroll
    for (int j = 0; j < 8; j++) {
        int col = h * DHEAD + j * 8 + 2 * (lane & 3);
        size_t i0 = (size_t)(b * SEQ + row0) * EMB + col;
        size_t i1 = (size_t)(b * SEQ + row0 + 8) * EMB + col;
        __nv_bfloat16 h0, h1, lo0, lo1;
        split2(o[j][0] * inv0, h0, lo0); split2(o[j][1] * inv0, h1, lo1);
        *(uint32_t*)(g_Oh + i0) = pack2(h0, h1);
        *(uint32_t*)(g_Ol + i0) = pack2(lo0, lo1);
        split2(o[j][2] * inv1, h0, lo0); split2(o[j][3] * inv1, h1, lo1);
        *(uint32_t*)(g_Oh + i1) = pack2(h0, h1);
        *(uint32_t*)(g_Ol + i1) = pack2(lo0, lo1);
    }
}

// ---------------- launch ------------------------------------------------------
extern "C" void kernel_launch(void* const* d_in, const int* in_sizes, int n_in,
                              void* d_out, int out_size)
{
    const float* x     = (const float*)d_in[0];
    const float* tx    = (const float*)d_in[1];
    const float* Wqkv  = (const float*)d_in[2];
    const float* Wtqkv = (const float*)d_in[3];
    const float* Wout  = (const float*)d_in[4];
    float* out = (float*)d_out;

    cudaFuncSetAttribute(gemm_proj3, cudaFuncAttributeMaxDynamicSharedMemorySize, GSMEM);
    cudaFuncSetAttribute(gemm_out,   cudaFuncAttributeMaxDynamicSharedMemorySize, GSMEM);
    cudaFuncSetAttribute(flash_attn, cudaFuncAttributeMaxDynamicSharedMemorySize, FSMEM);

    int tot = CONVQ + PERMN;
    prep_kernel<<<(tot + 255) / 256, 256>>>(x, tx, Wout, Wqkv, Wtqkv);

    gemm_proj3<<<dim3(EMB/128, MROWS/128, 3), 256, GSMEM>>>();

    flash_attn<<<dim3(SEQ/128, NSLICE), 256, FSMEM>>>();

    gemm_out<<<dim3(EMB/128, MROWS/128), 256, GSMEM>>>(out);
}

// round 15
// speedup vs baseline: 1.0791x; 1.0791x over previous
#include <cuda_runtime.h>
#include <cuda_bf16.h>
#include <math.h>
#include <stdint.h>

#define BATCH 2
#define SEQ   2048
#define EMB   1024
#define HEADS 16
#define DHEAD 64
#define MROWS (BATCH*SEQ)         // 4096
#define NSLICE (BATCH*HEADS)      // 32

// ---------------- scratch (static device globals; no allocation) -------------
__device__ __nv_bfloat16 g_xh [MROWS*EMB], g_xl [MROWS*EMB];
__device__ __nv_bfloat16 g_txh[MROWS*EMB], g_txl[MROWS*EMB];
__device__ __nv_bfloat16 g_Kh [MROWS*EMB], g_Kl [MROWS*EMB];
__device__ __nv_bfloat16 g_TQh[MROWS*EMB], g_TQl[MROWS*EMB];
__device__ __nv_bfloat16 g_Vth[NSLICE*DHEAD*SEQ], g_Vtl[NSLICE*DHEAD*SEQ];
__device__ __nv_bfloat16 g_Oh [MROWS*EMB], g_Ol [MROWS*EMB];
__device__ __nv_bfloat16 g_Wkh [EMB*EMB], g_Wkl [EMB*EMB];
__device__ __nv_bfloat16 g_Wvh [EMB*EMB], g_Wvl [EMB*EMB];
__device__ __nv_bfloat16 g_Wtqh[EMB*EMB], g_Wtql[EMB*EMB];
__device__ __nv_bfloat16 g_Wouth[EMB*EMB], g_Woutl[EMB*EMB];

// ---------------- small helpers ----------------------------------------------
__device__ __forceinline__ uint32_t smem_u32(const void* p) {
    uint32_t a;
    asm("{ .reg .u64 t; cvta.to.shared.u64 t, %1; cvt.u32.u64 %0, t; }" : "=r"(a) : "l"(p));
    return a;
}
#define CP_ASYNC16(dst, src) \
    asm volatile("cp.async.cg.shared.global [%0], [%1], 16;" :: "r"(dst), "l"(src) : "memory")
#define CP_COMMIT() asm volatile("cp.async.commit_group;" ::: "memory")
#define CP_WAIT2()  asm volatile("cp.async.wait_group 2;" ::: "memory")
#define CP_WAIT1()  asm volatile("cp.async.wait_group 1;" ::: "memory")
#define CP_WAIT0()  asm volatile("cp.async.wait_group 0;" ::: "memory")

__device__ __forceinline__ void ldsm_x4(uint32_t r[4], uint32_t addr) {
    asm volatile("ldmatrix.sync.aligned.m8n8.x4.shared.b16 {%0,%1,%2,%3}, [%4];"
                 : "=r"(r[0]), "=r"(r[1]), "=r"(r[2]), "=r"(r[3]) : "r"(addr));
}
__device__ __forceinline__ void mma16816(float c[4], const uint32_t a[4],
                                         uint32_t b0, uint32_t b1) {
    asm volatile("mma.sync.aligned.m16n8k16.row.col.f32.bf16.bf16.f32 "
                 "{%0,%1,%2,%3},{%4,%5,%6,%7},{%8,%9},{%0,%1,%2,%3};"
                 : "+f"(c[0]), "+f"(c[1]), "+f"(c[2]), "+f"(c[3])
                 : "r"(a[0]), "r"(a[1]), "r"(a[2]), "r"(a[3]), "r"(b0), "r"(b1));
}
__device__ __forceinline__ uint32_t pack2(__nv_bfloat16 a, __nv_bfloat16 b) {
    return (uint32_t)__bfloat16_as_ushort(a) | ((uint32_t)__bfloat16_as_ushort(b) << 16);
}
__device__ __forceinline__ void split2(float x, __nv_bfloat16& h, __nv_bfloat16& l) {
    h = __float2bfloat16(x);
    l = __float2bfloat16(x - __bfloat162float(h));
}
__device__ __forceinline__ float ex2f(float x) {
    float r;
    asm("ex2.approx.ftz.f32 %0, %1;" : "=f"(r) : "f"(x));
    return r;
}

// smem tile geometry
#define SSTR 80              // 32-half rows (projection GEMMs)
#define TB   (128*SSTR)      // 10240 (one 128x32 operand tile)
#define SSTR64 144           // 64-half rows (flash kernel), conflict-free
#define TILE_B (64*SSTR64)   // 9216

__device__ __forceinline__ void fill_rows(uint32_t dst, const __nv_bfloat16* src,
                                          int ld, int rows, int tid) {
    for (int j = tid; j < rows * 4; j += 256) {
        int r = j >> 2, cc = j & 3;
        CP_ASYNC16(dst + r * SSTR + cc * 16, src + (size_t)r * ld + cc * 8);
    }
}

// ---------------- prep: convert x/tx/Wout + permute/split Wqkv,Wtqkv ---------
#define NQ ((MROWS*EMB)/4)       // 1048576
#define WQ ((EMB*EMB)/4)         // 262144
#define CONVQ (2*NQ + WQ)        // 2359296
#define PERMN (EMB*EMB)          // 1048576

__global__ void prep_kernel(const float* __restrict__ X0, const float* __restrict__ X1,
                            const float* __restrict__ X2,
                            const float* __restrict__ Wqkv, const float* __restrict__ Wtqkv)
{
    int i = blockIdx.x * blockDim.x + threadIdx.x;
    if (i < CONVQ) {
        const float* X; __nv_bfloat16 *H, *L;
        if (i < NQ)          { X = X0; H = g_xh;  L = g_xl; }
        else if (i < 2 * NQ) { X = X1; H = g_txh; L = g_txl; i -= NQ; }
        else                 { X = X2; H = g_Wouth; L = g_Woutl; i -= 2 * NQ; }
        float4 v = ((const float4*)X)[i];
        __nv_bfloat16 h0, h1, h2, h3, l0, l1, l2, l3;
        split2(v.x, h0, l0); split2(v.y, h1, l1);
        split2(v.z, h2, l2); split2(v.w, h3, l3);
        ((uint2*)H)[i] = make_uint2(pack2(h0, h1), pack2(h2, h3));
        ((uint2*)L)[i] = make_uint2(pack2(l0, l1), pack2(l2, l3));
        return;
    }
    i -= CONVQ;
    if (i >= PERMN) return;
    int k = i & 1023, n = i >> 10;
    int h = n >> 6, d = n & 63;
    size_t dst = (size_t)n * EMB + k;
    float vk  = Wqkv [(size_t)(d * 48 + 16 + h) * EMB + k];
    float vv  = Wqkv [(size_t)(d * 48 + 32 + h) * EMB + k];
    float vtq = Wtqkv[(size_t)(d * 48 +  0 + h) * EMB + k];
    __nv_bfloat16 hh, ll;
    split2(vk,  hh, ll); g_Wkh [dst] = hh; g_Wkl [dst] = ll;
    split2(vv,  hh, ll); g_Wvh [dst] = hh; g_Wvl [dst] = ll;
    split2(vtq, hh, ll); g_Wtqh[dst] = hh; g_Wtql[dst] = ll;
}

// ---------------- GEMM core: fused 3-term k-slices, 2 stages (occ 2) ---------
// stage layout: [Ah | Al | Bh | Bl], each 128 rows x 32 halves (10240 B)
#define KCH  32
#define STG  (4*TB)        // 40960
#define GSMEM (2*STG)      // 81920

__device__ __forceinline__ void fill_all(uint32_t st,
    const __nv_bfloat16* Ah, const __nv_bfloat16* Al,
    const __nv_bfloat16* Bh, const __nv_bfloat16* Bl,
    int rowBase, int colBase, int k0, int tid)
{
    fill_rows(st,          Ah + (size_t)rowBase * EMB + k0, EMB, 128, tid);
    fill_rows(st + TB,     Al + (size_t)rowBase * EMB + k0, EMB, 128, tid);
    fill_rows(st + 2 * TB, Bh + (size_t)colBase * EMB + k0, EMB, 128, tid);
    fill_rows(st + 3 * TB, Bl + (size_t)colBase * EMB + k0, EMB, 128, tid);
}

// compute all 3 split terms over one BK=32 stage; each fragment loaded once.
// TERM-MAJOR issue order: every accumulator's RAW distance = 16 MMAs.
__device__ __forceinline__ void compute_all(uint32_t st, int wrow, int wcol,
                                            int lane, float (*cfr)[4])
{
    const int arow  = wrow + (lane & 15);
    const int acolh = (lane >> 4) * 8;
    const int brow  = wcol + (lane & 7) + ((lane >> 4) << 3);
    const int bcolh = ((lane >> 3) & 1) * 8;
#pragma unroll
    for (int ks = 0; ks < 2; ks++) {
        uint32_t ah[4][4], al[4][4], bh[2][4], bl[2][4];
#pragma unroll
        for (int mt = 0; mt < 4; mt++) {
            uint32_t off = (uint32_t)(arow + mt * 16) * SSTR + (acolh + ks * 16) * 2;
            ldsm_x4(ah[mt], st + off);
            ldsm_x4(al[mt], st + TB + off);
        }
#pragma unroll
        for (int np = 0; np < 2; np++) {
            uint32_t off = (uint32_t)(brow + np * 16) * SSTR + (bcolh + ks * 16) * 2;
            ldsm_x4(bh[np], st + 2 * TB + off);
            ldsm_x4(bl[np], st + 3 * TB + off);
        }
#pragma unroll
        for (int mt = 0; mt < 4; mt++)
#pragma unroll
            for (int np = 0; np < 2; np++) {
                mma16816(cfr[(mt * 2 + np) * 2 + 0], ah[mt], bh[np][0], bh[np][1]);
                mma16816(cfr[(mt * 2 + np) * 2 + 1], ah[mt], bh[np][2], bh[np][3]);
            }
#pragma unroll
        for (int mt = 0; mt < 4; mt++)
#pragma unroll
            for (int np = 0; np < 2; np++) {
                mma16816(cfr[(mt * 2 + np) * 2 + 0], al[mt], bh[np][0], bh[np][1]);
                mma16816(cfr[(mt * 2 + np) * 2 + 1], al[mt], bh[np][2], bh[np][3]);
            }
#pragma unroll
        for (int mt = 0; mt < 4; mt++)
#pragma unroll
            for (int np = 0; np < 2; np++) {
                mma16816(cfr[(mt * 2 + np) * 2 + 0], ah[mt], bl[np][0], bl[np][1]);
                mma16816(cfr[(mt * 2 + np) * 2 + 1], ah[mt], bl[np][2], bl[np][3]);
            }
    }
}

__device__ __forceinline__ void gemm_core(
    const __nv_bfloat16* Ah, const __nv_bfloat16* Al,
    const __nv_bfloat16* Bh, const __nv_bfloat16* Bl,
    int rowBase, int colBase, uint32_t sb, int tid, int lane,
    int wrow, int wcol, float (*cfr)[4])
{
    fill_all(sb,       Ah, Al, Bh, Bl, rowBase, colBase, 0,  tid); CP_COMMIT();
    fill_all(sb + STG, Ah, Al, Bh, Bl, rowBase, colBase, 32, tid); CP_COMMIT();
    for (int c = 0; c < KCH; c++) {
        if (c + 1 < KCH) CP_WAIT1(); else CP_WAIT0();
        __syncthreads();
        uint32_t st = sb + (c & 1) * STG;
        compute_all(st, wrow, wcol, lane, cfr);
        __syncthreads();
        if (c + 2 < KCH) {
            fill_all(st, Ah, Al, Bh, Bl, rowBase, colBase, (c + 2) << 5, tid);
            CP_COMMIT();
        }
    }
}

// ---------------- merged projection GEMM (z: 0=K split, 1=V->Vt, 2=TQ split) -
__global__ void __launch_bounds__(256, 2)
gemm_proj3()
{
    extern __shared__ char smem[];
    uint32_t sb = smem_u32(smem);
    const int tid = threadIdx.x, lane = tid & 31, warp = tid >> 5;
    const int rowBase = blockIdx.y * 128, colBase = blockIdx.x * 128;
    const int z = blockIdx.z;
    const int wrow = (warp >> 2) * 64, wcol = (warp & 3) * 32;

    const __nv_bfloat16 *Ah, *Al, *Bh, *Bl;
    if (z == 0)      { Ah = g_xh;  Al = g_xl;  Bh = g_Wkh;  Bl = g_Wkl;  }
    else if (z == 1) { Ah = g_xh;  Al = g_xl;  Bh = g_Wvh;  Bl = g_Wvl;  }
    else             { Ah = g_txh; Al = g_txl; Bh = g_Wtqh; Bl = g_Wtql; }

    float cfr[16][4];
#pragma unroll
    for (int i = 0; i < 16; i++)
#pragma unroll
        for (int j = 0; j < 4; j++) cfr[i][j] = 0.f;

    gemm_core(Ah, Al, Bh, Bl, rowBase, colBase, sb, tid, lane, wrow, wcol, cfr);

    if (z != 1) {
        __nv_bfloat16* H = (z == 0) ? g_Kh : g_TQh;
        __nv_bfloat16* L = (z == 0) ? g_Kl : g_TQl;
#pragma unroll
        for (int mt = 0; mt < 4; mt++)
#pragma unroll
            for (int np = 0; np < 2; np++)
#pragma unroll
                for (int t8 = 0; t8 < 2; t8++) {
                    int nt = np * 2 + t8;
                    int row = rowBase + wrow + mt * 16 + (lane >> 2);
                    int col = colBase + wcol + nt * 8 + 2 * (lane & 3);
                    float* cc = cfr[(mt * 2 + np) * 2 + t8];
#pragma unroll
                    for (int half = 0; half < 2; half++) {
                        int r = row + half * 8;
                        __nv_bfloat16 h0, h1, l0, l1;
                        split2(cc[half * 2], h0, l0); split2(cc[half * 2 + 1], h1, l1);
                        *(uint32_t*)(H + (size_t)r * EMB + col) = pack2(h0, h1);
                        *(uint32_t*)(L + (size_t)r * EMB + col) = pack2(l0, l1);
                    }
                }
    } else {
        // V: transpose in smem, write Vt[z][d][t] split bf16, t-coalesced
        CP_WAIT0();
        __syncthreads();
        float* tile = (float*)smem;   // [col][row], pitch 129: 66048 B <= 81920
#pragma unroll
        for (int mt = 0; mt < 4; mt++)
#pragma unroll
            for (int np = 0; np < 2; np++)
#pragma unroll
                for (int t8 = 0; t8 < 2; t8++) {
                    int nt = np * 2 + t8;
                    int rl = wrow + mt * 16 + (lane >> 2);
                    int cl = wcol + nt * 8 + 2 * (lane & 3);
                    float* cc = cfr[(mt * 2 + np) * 2 + t8];
#pragma unroll
                    for (int half = 0; half < 2; half++) {
                        tile[(cl + 0) * 129 + rl + half * 8] = cc[half * 2];
                        tile[(cl + 1) * 129 + rl + half * 8] = cc[half * 2 + 1];
                    }
                }
        __syncthreads();
        const int bb = rowBase >> 11, t0 = rowBase & 2047;
        for (int j = tid; j < 128 * 16; j += 256) {
            int c = j >> 4, tc = j & 15;
            int dg = colBase + c, hh = dg >> 6, dd = dg & 63;
            size_t dst = (((size_t)(bb * 16 + hh)) * DHEAD + dd) * SEQ + t0 + tc * 8;
            uint32_t hv[4], lv[4];
#pragma unroll
            for (int u = 0; u < 4; u++) {
                float v0 = tile[c * 129 + tc * 8 + 2 * u];
                float v1 = tile[c * 129 + tc * 8 + 2 * u + 1];
                __nv_bfloat16 h0, l0, h1, l1;
                split2(v0, h0, l0); split2(v1, h1, l1);
                hv[u] = pack2(h0, h1); lv[u] = pack2(l0, l1);
            }
            *(uint4*)(g_Vth + dst) = make_uint4(hv[0], hv[1], hv[2], hv[3]);
            *(uint4*)(g_Vtl + dst) = make_uint4(lv[0], lv[1], lv[2], lv[3]);
        }
    }
}

// ---------------- output GEMM (fp32 out) -------------------------------------
__global__ void __launch_bounds__(256, 2)
gemm_out(float* __restrict__ C)
{
    extern __shared__ char smem[];
    uint32_t sb = smem_u32(smem);
    const int tid = threadIdx.x, lane = tid & 31, warp = tid >> 5;
    const int rowBase = blockIdx.y * 128, colBase = blockIdx.x * 128;
    const int wrow = (warp >> 2) * 64, wcol = (warp & 3) * 32;

    float cfr[16][4];
#pragma unroll
    for (int i = 0; i < 16; i++)
#pragma unroll
        for (int j = 0; j < 4; j++) cfr[i][j] = 0.f;

    gemm_core(g_Oh, g_Ol, g_Wouth, g_Woutl, rowBase, colBase, sb, tid, lane, wrow, wcol, cfr);

#pragma unroll
    for (int mt = 0; mt < 4; mt++)
#pragma unroll
        for (int np = 0; np < 2; np++)
#pragma unroll
            for (int t8 = 0; t8 < 2; t8++) {
                int nt = np * 2 + t8;
                int row = rowBase + wrow + mt * 16 + (lane >> 2);
                int col = colBase + wcol + nt * 8 + 2 * (lane & 3);
                float* cc = cfr[(mt * 2 + np) * 2 + t8];
#pragma unroll
                for (int half = 0; half < 2; half++) {
                    int r = row + half * 8;
                    *(float2*)(C + (size_t)r * EMB + col) =
                        make_float2(cc[half * 2], cc[half * 2 + 1]);
                }
            }
}

// ---------------- fused flash attention (HMMA, 3-term split, 3-stage) --------
#define FSTAGE (4*TILE_B)    // 36864
#define FSMEM  (3*FSTAGE)    // 110592
#define NT     (SEQ/64)      // 32
#define SCALE2 11.5415603271862624f   // 8 * log2(e)

__device__ __forceinline__ void fill_kv(uint32_t st, int t, int b, int h, int z, int tid)
{
    const size_t koff = (size_t)(b * SEQ + t * 64) * EMB + h * DHEAD;
    const size_t voff = (size_t)z * DHEAD * SEQ + t * 64;
    for (int j = tid; j < 64 * 8; j += 256) {
        int r = j >> 3, c = j & 7;
        uint32_t d = (uint32_t)r * SSTR64 + c * 16;
        size_t ko = koff + (size_t)r * EMB + c * 8;
        size_t vo = voff + (size_t)r * SEQ + c * 8;
        CP_ASYNC16(st + d,              g_Kh  + ko);
        CP_ASYNC16(st + TILE_B + d,     g_Kl  + ko);
        CP_ASYNC16(st + 2 * TILE_B + d, g_Vth + vo);
        CP_ASYNC16(st + 3 * TILE_B + d, g_Vtl + vo);
    }
}

__device__ __forceinline__ void mma_pass(uint32_t bbase, const uint32_t A[4][4],
                                         float (*s)[4], int lane)
{
    const int brow  = (lane & 7) + ((lane >> 4) << 3);
    const int bcolh = ((lane >> 3) & 1) * 8;
#pragma unroll
    for (int ks = 0; ks < 4; ks++) {
#pragma unroll
        for (int pr = 0; pr < 4; pr++) {
            uint32_t bf[4];
            ldsm_x4(bf, bbase + (uint32_t)(brow + pr * 16) * SSTR64 + (bcolh + ks * 16) * 2);
            mma16816(s[pr * 2 + 0], A[ks], bf[0], bf[1]);
            mma16816(s[pr * 2 + 1], A[ks], bf[2], bf[3]);
        }
    }
}

__device__ __forceinline__ void mma_pass2(uint32_t bbase, const uint32_t A1[4][4],
                                          const uint32_t A2[4][4],
                                          float (*s)[4], int lane)
{
    const int brow  = (lane & 7) + ((lane >> 4) << 3);
    const int bcolh = ((lane >> 3) & 1) * 8;
#pragma unroll
    for (int ks = 0; ks < 4; ks++) {
#pragma unroll
        for (int pr = 0; pr < 4; pr++) {
            uint32_t bf[4];
            ldsm_x4(bf, bbase + (uint32_t)(brow + pr * 16) * SSTR64 + (bcolh + ks * 16) * 2);
            mma16816(s[pr * 2 + 0], A1[ks], bf[0], bf[1]);
            mma16816(s[pr * 2 + 1], A1[ks], bf[2], bf[3]);
            mma16816(s[pr * 2 + 0], A2[ks], bf[0], bf[1]);
            mma16816(s[pr * 2 + 1], A2[ks], bf[2], bf[3]);
        }
    }
}

__device__ __forceinline__ void pv2_pass(uint32_t bbase, const float (*s)[4],
                                         float (*o)[4], int lane)
{
    const int brow  = (lane & 7) + ((lane >> 4) << 3);
    const int bcolh = ((lane >> 3) & 1) * 8;
#pragma unroll
    for (int ks = 0; ks < 4; ks++) {
        const float* c0 = s[2 * ks];
        const float* c1 = s[2 * ks + 1];
        uint32_t Ah[4], Al[4];
        {
            __nv_bfloat16 hA, lA, hB, lB;
            split2(c0[0], hA, lA); split2(c0[1], hB, lB);
            Ah[0] = pack2(hA, hB); Al[0] = pack2(lA, lB);
            split2(c0[2], hA, lA); split2(c0[3], hB, lB);
            Ah[1] = pack2(hA, hB); Al[1] = pack2(lA, lB);
            split2(c1[0], hA, lA); split2(c1[1], hB, lB);
            Ah[2] = pack2(hA, hB); Al[2] = pack2(lA, lB);
            split2(c1[2], hA, lA); split2(c1[3], hB, lB);
            Ah[3] = pack2(hA, hB); Al[3] = pack2(lA, lB);
        }
#pragma unroll
        for (int pr = 0; pr < 4; pr++) {
            uint32_t bf[4];
            ldsm_x4(bf, bbase + (uint32_t)(brow + pr * 16) * SSTR64 + (bcolh + ks * 16) * 2);
            mma16816(o[pr * 2 + 0], Ah, bf[0], bf[1]);
            mma16816(o[pr * 2 + 1], Ah, bf[2], bf[3]);
            mma16816(o[pr * 2 + 0], Al, bf[0], bf[1]);
            mma16816(o[pr * 2 + 1], Al, bf[2], bf[3]);
        }
    }
}

__device__ __forceinline__ void pv_hi_pass(uint32_t bbase, const float (*s)[4],
                                           float (*o)[4], int lane)
{
    const int brow  = (lane & 7) + ((lane >> 4) << 3);
    const int bcolh = ((lane >> 3) & 1) * 8;
#pragma unroll
    for (int ks = 0; ks < 4; ks++) {
        const float* c0 = s[2 * ks];
        const float* c1 = s[2 * ks + 1];
        uint32_t Ah[4];
        Ah[0] = pack2(__float2bfloat16(c0[0]), __float2bfloat16(c0[1]));
        Ah[1] = pack2(__float2bfloat16(c0[2]), __float2bfloat16(c0[3]));
        Ah[2] = pack2(__float2bfloat16(c1[0]), __float2bfloat16(c1[1]));
        Ah[3] = pack2(__float2bfloat16(c1[2]), __float2bfloat16(c1[3]));
#pragma unroll
        for (int pr = 0; pr < 4; pr++) {
            uint32_t bf[4];
            ldsm_x4(bf, bbase + (uint32_t)(brow + pr * 16) * SSTR64 + (bcolh + ks * 16) * 2);
            mma16816(o[pr * 2 + 0], Ah, bf[0], bf[1]);
            mma16816(o[pr * 2 + 1], Ah, bf[2], bf[3]);
        }
    }
}

__global__ void __launch_bounds__(256, 2)
flash_attn()
{
    extern __shared__ char smem[];
    uint32_t sb = smem_u32(smem);
    const int tid = threadIdx.x, lane = tid & 31, warp = tid >> 5;
    const int rowBase = blockIdx.x * 128;
    const int z = blockIdx.y, b = z >> 4, h = z & 15;
    const int wrow = warp * 16;
    const int arow  = wrow + (lane & 15);
    const int acolh = (lane >> 4) * 8;

    // stage TQ (hi into stage0 low half, lo into stage0 high half)
    {
        const size_t toff = (size_t)(b * SEQ + rowBase) * EMB + h * DHEAD;
        for (int j = tid; j < 128 * 8; j += 256) {
            int r = j >> 3, c = j & 7;
            uint32_t d = (uint32_t)r * SSTR64 + c * 16;
            size_t go = toff + (size_t)r * EMB + c * 8;
            CP_ASYNC16(sb + d,         g_TQh + go);
            CP_ASYNC16(sb + 18432 + d, g_TQl + go);
        }
        CP_COMMIT(); CP_WAIT0();
    }
    __syncthreads();

    uint32_t aqh[4][4], aql[4][4];
#pragma unroll
    for (int ks = 0; ks < 4; ks++) {
        ldsm_x4(aqh[ks], sb + (uint32_t)arow * SSTR64 + (acolh + ks * 16) * 2);
        ldsm_x4(aql[ks], sb + 18432 + (uint32_t)arow * SSTR64 + (acolh + ks * 16) * 2);
    }
    __syncthreads();   // stage0 free for K/V

    float o[8][4];
#pragma unroll
    for (int i = 0; i < 8; i++)
#pragma unroll
        for (int j = 0; j < 4; j++) o[i][j] = 0.f;
    float m0 = -INFINITY, m1 = -INFINITY, l0 = 0.f, l1 = 0.f;

    fill_kv(sb, 0, b, h, z, tid);           CP_COMMIT();
    fill_kv(sb + FSTAGE, 1, b, h, z, tid);  CP_COMMIT();

    uint32_t stv[3] = {sb, sb + FSTAGE, sb + 2 * FSTAGE};
    for (int t = 0; t < NT; t++) {
        if (t + 1 < NT) { CP_WAIT1(); } else { CP_WAIT0(); }
        __syncthreads();   // all warps done with stage (t-1)%3 before refill
        if (t + 2 < NT) {
            fill_kv(stv[(t + 2) % 3], t + 2, b, h, z, tid);
            CP_COMMIT();
        }
        uint32_t st = stv[t % 3];

        float s[8][4];
#pragma unroll
        for (int i = 0; i < 8; i++)
#pragma unroll
            for (int j = 0; j < 4; j++) s[i][j] = 0.f;
        mma_pass2(st, aqh, aql, s, lane);      // (TQh + TQl) . Kh, Kh loaded once
        mma_pass(st + TILE_B, aqh, s, lane);   // TQh . Kl

        // online softmax in exp2 domain (scores scaled by 8*log2 e)
        float rm0 = -INFINITY, rm1 = -INFINITY;
#pragma unroll
        for (int i = 0; i < 8; i++) {
            s[i][0] *= SCALE2; s[i][1] *= SCALE2; s[i][2] *= SCALE2; s[i][3] *= SCALE2;
            rm0 = fmaxf(rm0, fmaxf(s[i][0], s[i][1]));
            rm1 = fmaxf(rm1, fmaxf(s[i][2], s[i][3]));
        }
        rm0 = fmaxf(rm0, __shfl_xor_sync(0xffffffffu, rm0, 1));
        rm0 = fmaxf(rm0, __shfl_xor_sync(0xffffffffu, rm0, 2));
        rm1 = fmaxf(rm1, __shfl_xor_sync(0xffffffffu, rm1, 1));
        rm1 = fmaxf(rm1, __shfl_xor_sync(0xffffffffu, rm1, 2));
        float mn0 = fmaxf(m0, rm0), mn1 = fmaxf(m1, rm1);
        float c0 = ex2f(m0 - mn0), c1 = ex2f(m1 - mn1);
        l0 *= c0; l1 *= c1;
#pragma unroll
        for (int i = 0; i < 8; i++) {
            o[i][0] *= c0; o[i][1] *= c0; o[i][2] *= c1; o[i][3] *= c1;
            float p0 = ex2f(s[i][0] - mn0), p1 = ex2f(s[i][1] - mn0);
            float p2 = ex2f(s[i][2] - mn1), p3 = ex2f(s[i][3] - mn1);
            s[i][0] = p0; s[i][1] = p1; s[i][2] = p2; s[i][3] = p3;
            l0 += p0 + p1; l1 += p2 + p3;
        }
        m0 = mn0; m1 = mn1;

        pv2_pass(st + 2 * TILE_B, s, o, lane);    // (Ph + Pl) . Vh, Vh loaded once
        pv_hi_pass(st + 3 * TILE_B, s, o, lane);  // Ph . Vl
        // no trailing sync: next iteration's top barrier guards stage reuse
    }

    l0 += __shfl_xor_sync(0xffffffffu, l0, 1);
    l0 += __shfl_xor_sync(0xffffffffu, l0, 2);
    l1 += __shfl_xor_sync(0xffffffffu, l1, 1);
    l1 += __shfl_xor_sync(0xffffffffu, l1, 2);
    float inv0 = 1.f / l0, inv1 = 1.f / l1;

    const int row0 = rowBase + wrow + (lane >> 2);
#pragma unroll
    for (int j = 0; j < 8; j++) {
        int col = h * DHEAD + j * 8 + 2 * (lane & 3);
        size_t i0 = (size_t)(b * SEQ + row0) * EMB + col;
        size_t i1 = (size_t)(b * SEQ + row0 + 8) * EMB + col;
        __nv_bfloat16 h0, h1, lo0, lo1;
        split2(o[j][0] * inv0, h0, lo0); split2(o[j][1] * inv0, h1, lo1);
        *(uint32_t*)(g_Oh + i0) = pack2(h0, h1);
        *(uint32_t*)(g_Ol + i0) = pack2(lo0, lo1);
        split2(o[j][2] * inv1, h0, lo0); split2(o[j][3] * inv1, h1, lo1);
        *(uint32_t*)(g_Oh + i1) = pack2(h0, h1);
        *(uint32_t*)(g_Ol + i1) = pack2(lo0, lo1);
    }
}

// ---------------- launch ------------------------------------------------------
extern "C" void kernel_launch(void* const* d_in, const int* in_sizes, int n_in,
                              void* d_out, int out_size)
{
    const float* x     = (const float*)d_in[0];
    const float* tx    = (const float*)d_in[1];
    const float* Wqkv  = (const float*)d_in[2];
    const float* Wtqkv = (const float*)d_in[3];
    const float* Wout  = (const float*)d_in[4];
    float* out = (float*)d_out;

    cudaFuncSetAttribute(gemm_proj3, cudaFuncAttributeMaxDynamicSharedMemorySize, GSMEM);
    cudaFuncSetAttribute(gemm_out,   cudaFuncAttributeMaxDynamicSharedMemorySize, GSMEM);
    cudaFuncSetAttribute(flash_attn, cudaFuncAttributeMaxDynamicSharedMemorySize, FSMEM);

    int tot = CONVQ + PERMN;
    prep_kernel<<<(tot + 255) / 256, 256>>>(x, tx, Wout, Wqkv, Wtqkv);

    gemm_proj3<<<dim3(EMB/128, MROWS/128, 3), 256, GSMEM>>>();

    flash_attn<<<dim3(SEQ/128, NSLICE), 256, FSMEM>>>();

    gemm_out<<<dim3(EMB/128, MROWS/128), 256, GSMEM>>>(out);
}

// round 16
// speedup vs baseline: 1.1200x; 1.0379x over previous
#include <cuda_runtime.h>
#include <cuda_bf16.h>
#include <math.h>
#include <stdint.h>

#define BATCH 2
#define SEQ   2048
#define EMB   1024
#define HEADS 16
#define DHEAD 64
#define MROWS (BATCH*SEQ)         // 4096
#define NSLICE (BATCH*HEADS)      // 32

// ---------------- scratch (static device globals; no allocation) -------------
__device__ __nv_bfloat16 g_xh [MROWS*EMB], g_xl [MROWS*EMB];
__device__ __nv_bfloat16 g_txh[MROWS*EMB], g_txl[MROWS*EMB];
__device__ __nv_bfloat16 g_Kh [MROWS*EMB], g_Kl [MROWS*EMB];
__device__ __nv_bfloat16 g_TQh[MROWS*EMB], g_TQl[MROWS*EMB];
__device__ __nv_bfloat16 g_Vth[NSLICE*DHEAD*SEQ], g_Vtl[NSLICE*DHEAD*SEQ];
__device__ __nv_bfloat16 g_Oh [MROWS*EMB], g_Ol [MROWS*EMB];
__device__ __nv_bfloat16 g_Wkh [EMB*EMB], g_Wkl [EMB*EMB];
__device__ __nv_bfloat16 g_Wvh [EMB*EMB], g_Wvl [EMB*EMB];
__device__ __nv_bfloat16 g_Wtqh[EMB*EMB], g_Wtql[EMB*EMB];
__device__ __nv_bfloat16 g_Wouth[EMB*EMB], g_Woutl[EMB*EMB];

// ---------------- small helpers ----------------------------------------------
__device__ __forceinline__ uint32_t smem_u32(const void* p) {
    uint32_t a;
    asm("{ .reg .u64 t; cvta.to.shared.u64 t, %1; cvt.u32.u64 %0, t; }" : "=r"(a) : "l"(p));
    return a;
}
#define CP_ASYNC16(dst, src) \
    asm volatile("cp.async.cg.shared.global [%0], [%1], 16;" :: "r"(dst), "l"(src) : "memory")
#define CP_COMMIT() asm volatile("cp.async.commit_group;" ::: "memory")
#define CP_WAIT2()  asm volatile("cp.async.wait_group 2;" ::: "memory")
#define CP_WAIT1()  asm volatile("cp.async.wait_group 1;" ::: "memory")
#define CP_WAIT0()  asm volatile("cp.async.wait_group 0;" ::: "memory")

__device__ __forceinline__ void ldsm_x4(uint32_t r[4], uint32_t addr) {
    asm volatile("ldmatrix.sync.aligned.m8n8.x4.shared.b16 {%0,%1,%2,%3}, [%4];"
                 : "=r"(r[0]), "=r"(r[1]), "=r"(r[2]), "=r"(r[3]) : "r"(addr));
}
__device__ __forceinline__ void mma16816(float c[4], const uint32_t a[4],
                                         uint32_t b0, uint32_t b1) {
    asm volatile("mma.sync.aligned.m16n8k16.row.col.f32.bf16.bf16.f32 "
                 "{%0,%1,%2,%3},{%4,%5,%6,%7},{%8,%9},{%0,%1,%2,%3};"
                 : "+f"(c[0]), "+f"(c[1]), "+f"(c[2]), "+f"(c[3])
                 : "r"(a[0]), "r"(a[1]), "r"(a[2]), "r"(a[3]), "r"(b0), "r"(b1));
}
__device__ __forceinline__ uint32_t pack2(__nv_bfloat16 a, __nv_bfloat16 b) {
    return (uint32_t)__bfloat16_as_ushort(a) | ((uint32_t)__bfloat16_as_ushort(b) << 16);
}
__device__ __forceinline__ void split2(float x, __nv_bfloat16& h, __nv_bfloat16& l) {
    h = __float2bfloat16(x);
    l = __float2bfloat16(x - __bfloat162float(h));
}
// packed: {lo=cvt(x0), hi=cvt(x1)} in one instruction
__device__ __forceinline__ uint32_t cvt2(float x0, float x1) {
    uint32_t r;
    asm("cvt.rn.bf16x2.f32 %0, %1, %2;" : "=r"(r) : "f"(x1), "f"(x0));
    return r;
}
// packed hi/lo split of a pair (identical rounding to scalar split2)
__device__ __forceinline__ void split2pair(float x0, float x1,
                                           uint32_t& hp, uint32_t& lp) {
    hp = cvt2(x0, x1);
    float h0 = __uint_as_float(hp << 16);
    float h1 = __uint_as_float(hp & 0xffff0000u);
    lp = cvt2(x0 - h0, x1 - h1);
}
__device__ __forceinline__ float ex2f(float x) {
    float r;
    asm("ex2.approx.ftz.f32 %0, %1;" : "=f"(r) : "f"(x));
    return r;
}

// smem tile geometry
#define SSTR 80              // 32-half rows (projection GEMMs)
#define TB   (128*SSTR)      // 10240 (one 128x32 operand tile)
#define SSTR64 144           // 64-half rows (flash kernel), conflict-free
#define TILE_B (64*SSTR64)   // 9216

__device__ __forceinline__ void fill_rows(uint32_t dst, const __nv_bfloat16* src,
                                          int ld, int rows, int tid) {
    for (int j = tid; j < rows * 4; j += 256) {
        int r = j >> 2, cc = j & 3;
        CP_ASYNC16(dst + r * SSTR + cc * 16, src + (size_t)r * ld + cc * 8);
    }
}

// ---------------- prep: convert x/tx/Wout + permute/split Wqkv,Wtqkv ---------
#define NQ ((MROWS*EMB)/4)       // 1048576
#define WQ ((EMB*EMB)/4)         // 262144
#define CONVQ (2*NQ + WQ)        // 2359296
#define PERMN (EMB*EMB)          // 1048576

__global__ void prep_kernel(const float* __restrict__ X0, const float* __restrict__ X1,
                            const float* __restrict__ X2,
                            const float* __restrict__ Wqkv, const float* __restrict__ Wtqkv)
{
    int i = blockIdx.x * blockDim.x + threadIdx.x;
    if (i < CONVQ) {
        const float* X; __nv_bfloat16 *H, *L;
        if (i < NQ)          { X = X0; H = g_xh;  L = g_xl; }
        else if (i < 2 * NQ) { X = X1; H = g_txh; L = g_txl; i -= NQ; }
        else                 { X = X2; H = g_Wouth; L = g_Woutl; i -= 2 * NQ; }
        float4 v = ((const float4*)X)[i];
        uint32_t h01, l01, h23, l23;
        split2pair(v.x, v.y, h01, l01);
        split2pair(v.z, v.w, h23, l23);
        ((uint2*)H)[i] = make_uint2(h01, h23);
        ((uint2*)L)[i] = make_uint2(l01, l23);
        return;
    }
    i -= CONVQ;
    if (i >= PERMN) return;
    int k = i & 1023, n = i >> 10;
    int h = n >> 6, d = n & 63;
    size_t dst = (size_t)n * EMB + k;
    float vk  = Wqkv [(size_t)(d * 48 + 16 + h) * EMB + k];
    float vv  = Wqkv [(size_t)(d * 48 + 32 + h) * EMB + k];
    float vtq = Wtqkv[(size_t)(d * 48 +  0 + h) * EMB + k];
    __nv_bfloat16 hh, ll;
    split2(vk,  hh, ll); g_Wkh [dst] = hh; g_Wkl [dst] = ll;
    split2(vv,  hh, ll); g_Wvh [dst] = hh; g_Wvl [dst] = ll;
    split2(vtq, hh, ll); g_Wtqh[dst] = hh; g_Wtql[dst] = ll;
}

// ---------------- GEMM core: fused 3-term k-slices, 2 stages (occ 2) ---------
#define KCH  32
#define STG  (4*TB)        // 40960
#define GSMEM (2*STG)      // 81920

__device__ __forceinline__ void fill_all(uint32_t st,
    const __nv_bfloat16* Ah, const __nv_bfloat16* Al,
    const __nv_bfloat16* Bh, const __nv_bfloat16* Bl,
    int rowBase, int colBase, int k0, int tid)
{
    fill_rows(st,          Ah + (size_t)rowBase * EMB + k0, EMB, 128, tid);
    fill_rows(st + TB,     Al + (size_t)rowBase * EMB + k0, EMB, 128, tid);
    fill_rows(st + 2 * TB, Bh + (size_t)colBase * EMB + k0, EMB, 128, tid);
    fill_rows(st + 3 * TB, Bl + (size_t)colBase * EMB + k0, EMB, 128, tid);
}

__device__ __forceinline__ void compute_all(uint32_t st, int wrow, int wcol,
                                            int lane, float (*cfr)[4])
{
    const int arow  = wrow + (lane & 15);
    const int acolh = (lane >> 4) * 8;
    const int brow  = wcol + (lane & 7) + ((lane >> 4) << 3);
    const int bcolh = ((lane >> 3) & 1) * 8;
#pragma unroll
    for (int ks = 0; ks < 2; ks++) {
        uint32_t ah[4][4], al[4][4], bh[2][4], bl[2][4];
#pragma unroll
        for (int mt = 0; mt < 4; mt++) {
            uint32_t off = (uint32_t)(arow + mt * 16) * SSTR + (acolh + ks * 16) * 2;
            ldsm_x4(ah[mt], st + off);
            ldsm_x4(al[mt], st + TB + off);
        }
#pragma unroll
        for (int np = 0; np < 2; np++) {
            uint32_t off = (uint32_t)(brow + np * 16) * SSTR + (bcolh + ks * 16) * 2;
            ldsm_x4(bh[np], st + 2 * TB + off);
            ldsm_x4(bl[np], st + 3 * TB + off);
        }
#pragma unroll
        for (int mt = 0; mt < 4; mt++)
#pragma unroll
            for (int np = 0; np < 2; np++) {
                mma16816(cfr[(mt * 2 + np) * 2 + 0], ah[mt], bh[np][0], bh[np][1]);
                mma16816(cfr[(mt * 2 + np) * 2 + 1], ah[mt], bh[np][2], bh[np][3]);
            }
#pragma unroll
        for (int mt = 0; mt < 4; mt++)
#pragma unroll
            for (int np = 0; np < 2; np++) {
                mma16816(cfr[(mt * 2 + np) * 2 + 0], al[mt], bh[np][0], bh[np][1]);
                mma16816(cfr[(mt * 2 + np) * 2 + 1], al[mt], bh[np][2], bh[np][3]);
            }
#pragma unroll
        for (int mt = 0; mt < 4; mt++)
#pragma unroll
            for (int np = 0; np < 2; np++) {
                mma16816(cfr[(mt * 2 + np) * 2 + 0], ah[mt], bl[np][0], bl[np][1]);
                mma16816(cfr[(mt * 2 + np) * 2 + 1], ah[mt], bl[np][2], bl[np][3]);
            }
    }
}

__device__ __forceinline__ void gemm_core(
    const __nv_bfloat16* Ah, const __nv_bfloat16* Al,
    const __nv_bfloat16* Bh, const __nv_bfloat16* Bl,
    int rowBase, int colBase, uint32_t sb, int tid, int lane,
    int wrow, int wcol, float (*cfr)[4])
{
    fill_all(sb,       Ah, Al, Bh, Bl, rowBase, colBase, 0,  tid); CP_COMMIT();
    fill_all(sb + STG, Ah, Al, Bh, Bl, rowBase, colBase, 32, tid); CP_COMMIT();
    for (int c = 0; c < KCH; c++) {
        if (c + 1 < KCH) CP_WAIT1(); else CP_WAIT0();
        __syncthreads();
        uint32_t st = sb + (c & 1) * STG;
        compute_all(st, wrow, wcol, lane, cfr);
        __syncthreads();
        if (c + 2 < KCH) {
            fill_all(st, Ah, Al, Bh, Bl, rowBase, colBase, (c + 2) << 5, tid);
            CP_COMMIT();
        }
    }
}

// ---------------- merged projection GEMM (z: 0=K split, 1=V->Vt, 2=TQ split) -
__global__ void __launch_bounds__(256, 2)
gemm_proj3()
{
    extern __shared__ char smem[];
    uint32_t sb = smem_u32(smem);
    const int tid = threadIdx.x, lane = tid & 31, warp = tid >> 5;
    const int rowBase = blockIdx.y * 128, colBase = blockIdx.x * 128;
    const int z = blockIdx.z;
    const int wrow = (warp >> 2) * 64, wcol = (warp & 3) * 32;

    const __nv_bfloat16 *Ah, *Al, *Bh, *Bl;
    if (z == 0)      { Ah = g_xh;  Al = g_xl;  Bh = g_Wkh;  Bl = g_Wkl;  }
    else if (z == 1) { Ah = g_xh;  Al = g_xl;  Bh = g_Wvh;  Bl = g_Wvl;  }
    else             { Ah = g_txh; Al = g_txl; Bh = g_Wtqh; Bl = g_Wtql; }

    float cfr[16][4];
#pragma unroll
    for (int i = 0; i < 16; i++)
#pragma unroll
        for (int j = 0; j < 4; j++) cfr[i][j] = 0.f;

    gemm_core(Ah, Al, Bh, Bl, rowBase, colBase, sb, tid, lane, wrow, wcol, cfr);

    if (z != 1) {
        __nv_bfloat16* H = (z == 0) ? g_Kh : g_TQh;
        __nv_bfloat16* L = (z == 0) ? g_Kl : g_TQl;
#pragma unroll
        for (int mt = 0; mt < 4; mt++)
#pragma unroll
            for (int np = 0; np < 2; np++)
#pragma unroll
                for (int t8 = 0; t8 < 2; t8++) {
                    int nt = np * 2 + t8;
                    int row = rowBase + wrow + mt * 16 + (lane >> 2);
                    int col = colBase + wcol + nt * 8 + 2 * (lane & 3);
                    float* cc = cfr[(mt * 2 + np) * 2 + t8];
#pragma unroll
                    for (int half = 0; half < 2; half++) {
                        int r = row + half * 8;
                        uint32_t hp, lp;
                        split2pair(cc[half * 2], cc[half * 2 + 1], hp, lp);
                        *(uint32_t*)(H + (size_t)r * EMB + col) = hp;
                        *(uint32_t*)(L + (size_t)r * EMB + col) = lp;
                    }
                }
    } else {
        // V: transpose in smem, write Vt[z][d][t] split bf16, t-coalesced
        CP_WAIT0();
        __syncthreads();
        float* tile = (float*)smem;   // [col][row], pitch 129: 66048 B <= 81920
#pragma unroll
        for (int mt = 0; mt < 4; mt++)
#pragma unroll
            for (int np = 0; np < 2; np++)
#pragma unroll
                for (int t8 = 0; t8 < 2; t8++) {
                    int nt = np * 2 + t8;
                    int rl = wrow + mt * 16 + (lane >> 2);
                    int cl = wcol + nt * 8 + 2 * (lane & 3);
                    float* cc = cfr[(mt * 2 + np) * 2 + t8];
#pragma unroll
                    for (int half = 0; half < 2; half++) {
                        tile[(cl + 0) * 129 + rl + half * 8] = cc[half * 2];
                        tile[(cl + 1) * 129 + rl + half * 8] = cc[half * 2 + 1];
                    }
                }
        __syncthreads();
        const int bb = rowBase >> 11, t0 = rowBase & 2047;
        for (int j = tid; j < 128 * 16; j += 256) {
            int c = j >> 4, tc = j & 15;
            int dg = colBase + c, hh = dg >> 6, dd = dg & 63;
            size_t dst = (((size_t)(bb * 16 + hh)) * DHEAD + dd) * SEQ + t0 + tc * 8;
            uint32_t hv[4], lv[4];
#pragma unroll
            for (int u = 0; u < 4; u++) {
                float v0 = tile[c * 129 + tc * 8 + 2 * u];
                float v1 = tile[c * 129 + tc * 8 + 2 * u + 1];
                split2pair(v0, v1, hv[u], lv[u]);
            }
            *(uint4*)(g_Vth + dst) = make_uint4(hv[0], hv[1], hv[2], hv[3]);
            *(uint4*)(g_Vtl + dst) = make_uint4(lv[0], lv[1], lv[2], lv[3]);
        }
    }
}

// ---------------- output GEMM (fp32 out) -------------------------------------
__global__ void __launch_bounds__(256, 2)
gemm_out(float* __restrict__ C)
{
    extern __shared__ char smem[];
    uint32_t sb = smem_u32(smem);
    const int tid = threadIdx.x, lane = tid & 31, warp = tid >> 5;
    const int rowBase = blockIdx.y * 128, colBase = blockIdx.x * 128;
    const int wrow = (warp >> 2) * 64, wcol = (warp & 3) * 32;

    float cfr[16][4];
#pragma unroll
    for (int i = 0; i < 16; i++)
#pragma unroll
        for (int j = 0; j < 4; j++) cfr[i][j] = 0.f;

    gemm_core(g_Oh, g_Ol, g_Wouth, g_Woutl, rowBase, colBase, sb, tid, lane, wrow, wcol, cfr);

#pragma unroll
    for (int mt = 0; mt < 4; mt++)
#pragma unroll
        for (int np = 0; np < 2; np++)
#pragma unroll
            for (int t8 = 0; t8 < 2; t8++) {
                int nt = np * 2 + t8;
                int row = rowBase + wrow + mt * 16 + (lane >> 2);
                int col = colBase + wcol + nt * 8 + 2 * (lane & 3);
                float* cc = cfr[(mt * 2 + np) * 2 + t8];
#pragma unroll
                for (int half = 0; half < 2; half++) {
                    int r = row + half * 8;
                    *(float2*)(C + (size_t)r * EMB + col) =
                        make_float2(cc[half * 2], cc[half * 2 + 1]);
                }
            }
}

// ---------------- fused flash attention (HMMA, 3-term split, 3-stage) --------
#define FSTAGE (4*TILE_B)    // 36864
#define FSMEM  (3*FSTAGE)    // 110592
#define NT     (SEQ/64)      // 32
#define SCALE2 11.5415603271862624f   // 8 * log2(e)

__device__ __forceinline__ void fill_kv(uint32_t st, int t, int b, int h, int z, int tid)
{
    const size_t koff = (size_t)(b * SEQ + t * 64) * EMB + h * DHEAD;
    const size_t voff = (size_t)z * DHEAD * SEQ + t * 64;
    for (int j = tid; j < 64 * 8; j += 256) {
        int r = j >> 3, c = j & 7;
        uint32_t d = (uint32_t)r * SSTR64 + c * 16;
        size_t ko = koff + (size_t)r * EMB + c * 8;
        size_t vo = voff + (size_t)r * SEQ + c * 8;
        CP_ASYNC16(st + d,              g_Kh  + ko);
        CP_ASYNC16(st + TILE_B + d,     g_Kl  + ko);
        CP_ASYNC16(st + 2 * TILE_B + d, g_Vth + vo);
        CP_ASYNC16(st + 3 * TILE_B + d, g_Vtl + vo);
    }
}

__device__ __forceinline__ void mma_pass(uint32_t bbase, const uint32_t A[4][4],
                                         float (*s)[4], int lane)
{
    const int brow  = (lane & 7) + ((lane >> 4) << 3);
    const int bcolh = ((lane >> 3) & 1) * 8;
#pragma unroll
    for (int ks = 0; ks < 4; ks++) {
#pragma unroll
        for (int pr = 0; pr < 4; pr++) {
            uint32_t bf[4];
            ldsm_x4(bf, bbase + (uint32_t)(brow + pr * 16) * SSTR64 + (bcolh + ks * 16) * 2);
            mma16816(s[pr * 2 + 0], A[ks], bf[0], bf[1]);
            mma16816(s[pr * 2 + 1], A[ks], bf[2], bf[3]);
        }
    }
}

__device__ __forceinline__ void mma_pass2(uint32_t bbase, const uint32_t A1[4][4],
                                          const uint32_t A2[4][4],
                                          float (*s)[4], int lane)
{
    const int brow  = (lane & 7) + ((lane >> 4) << 3);
    const int bcolh = ((lane >> 3) & 1) * 8;
#pragma unroll
    for (int ks = 0; ks < 4; ks++) {
#pragma unroll
        for (int pr = 0; pr < 4; pr++) {
            uint32_t bf[4];
            ldsm_x4(bf, bbase + (uint32_t)(brow + pr * 16) * SSTR64 + (bcolh + ks * 16) * 2);
            mma16816(s[pr * 2 + 0], A1[ks], bf[0], bf[1]);
            mma16816(s[pr * 2 + 1], A1[ks], bf[2], bf[3]);
            mma16816(s[pr * 2 + 0], A2[ks], bf[0], bf[1]);
            mma16816(s[pr * 2 + 1], A2[ks], bf[2], bf[3]);
        }
    }
}

__device__ __forceinline__ void pv2_pass(uint32_t bbase, const float (*s)[4],
                                         float (*o)[4], int lane)
{
    const int brow  = (lane & 7) + ((lane >> 4) << 3);
    const int bcolh = ((lane >> 3) & 1) * 8;
#pragma unroll
    for (int ks = 0; ks < 4; ks++) {
        const float* c0 = s[2 * ks];
        const float* c1 = s[2 * ks + 1];
        uint32_t Ah[4], Al[4];
        split2pair(c0[0], c0[1], Ah[0], Al[0]);
        split2pair(c0[2], c0[3], Ah[1], Al[1]);
        split2pair(c1[0], c1[1], Ah[2], Al[2]);
        split2pair(c1[2], c1[3], Ah[3], Al[3]);
#pragma unroll
        for (int pr = 0; pr < 4; pr++) {
            uint32_t bf[4];
            ldsm_x4(bf, bbase + (uint32_t)(brow + pr * 16) * SSTR64 + (bcolh + ks * 16) * 2);
            mma16816(o[pr * 2 + 0], Ah, bf[0], bf[1]);
            mma16816(o[pr * 2 + 1], Ah, bf[2], bf[3]);
            mma16816(o[pr * 2 + 0], Al, bf[0], bf[1]);
            mma16816(o[pr * 2 + 1], Al, bf[2], bf[3]);
        }
    }
}

__device__ __forceinline__ void pv_hi_pass(uint32_t bbase, const float (*s)[4],
                                           float (*o)[4], int lane)
{
    const int brow  = (lane & 7) + ((lane >> 4) << 3);
    const int bcolh = ((lane >> 3) & 1) * 8;
#pragma unroll
    for (int ks = 0; ks < 4; ks++) {
        const float* c0 = s[2 * ks];
        const float* c1 = s[2 * ks + 1];
        uint32_t Ah[4];
        Ah[0] = cvt2(c0[0], c0[1]);
        Ah[1] = cvt2(c0[2], c0[3]);
        Ah[2] = cvt2(c1[0], c1[1]);
        Ah[3] = cvt2(c1[2], c1[3]);
#pragma unroll
        for (int pr = 0; pr < 4; pr++) {
            uint32_t bf[4];
            ldsm_x4(bf, bbase + (uint32_t)(brow + pr * 16) * SSTR64 + (bcolh + ks * 16) * 2);
            mma16816(o[pr * 2 + 0], Ah, bf[0], bf[1]);
            mma16816(o[pr * 2 + 1], Ah, bf[2], bf[3]);
        }
    }
}

__global__ void __launch_bounds__(256, 2)
flash_attn()
{
    extern __shared__ char smem[];
    uint32_t sb = smem_u32(smem);
    const int tid = threadIdx.x, lane = tid & 31, warp = tid >> 5;
    const int rowBase = blockIdx.x * 128;
    const int z = blockIdx.y, b = z >> 4, h = z & 15;
    const int wrow = warp * 16;
    const int arow  = wrow + (lane & 15);
    const int acolh = (lane >> 4) * 8;

    // stage TQ (hi into stage0 low half, lo into stage0 high half)
    {
        const size_t toff = (size_t)(b * SEQ + rowBase) * EMB + h * DHEAD;
        for (int j = tid; j < 128 * 8; j += 256) {
            int r = j >> 3, c = j & 7;
            uint32_t d = (uint32_t)r * SSTR64 + c * 16;
            size_t go = toff + (size_t)r * EMB + c * 8;
            CP_ASYNC16(sb + d,         g_TQh + go);
            CP_ASYNC16(sb + 18432 + d, g_TQl + go);
        }
        CP_COMMIT(); CP_WAIT0();
    }
    __syncthreads();

    uint32_t aqh[4][4], aql[4][4];
#pragma unroll
    for (int ks = 0; ks < 4; ks++) {
        ldsm_x4(aqh[ks], sb + (uint32_t)arow * SSTR64 + (acolh + ks * 16) * 2);
        ldsm_x4(aql[ks], sb + 18432 + (uint32_t)arow * SSTR64 + (acolh + ks * 16) * 2);
    }
    __syncthreads();   // stage0 free for K/V

    float o[8][4];
#pragma unroll
    for (int i = 0; i < 8; i++)
#pragma unroll
        for (int j = 0; j < 4; j++) o[i][j] = 0.f;
    float m0 = -INFINITY, m1 = -INFINITY, l0 = 0.f, l1 = 0.f;

    fill_kv(sb, 0, b, h, z, tid);           CP_COMMIT();
    fill_kv(sb + FSTAGE, 1, b, h, z, tid);  CP_COMMIT();

    uint32_t stv[3] = {sb, sb + FSTAGE, sb + 2 * FSTAGE};
    for (int t = 0; t < NT; t++) {
        if (t + 1 < NT) { CP_WAIT1(); } else { CP_WAIT0(); }
        __syncthreads();   // all warps done with stage (t-1)%3 before refill
        if (t + 2 < NT) {
            fill_kv(stv[(t + 2) % 3], t + 2, b, h, z, tid);
            CP_COMMIT();
        }
        uint32_t st = stv[t % 3];

        float s[8][4];
#pragma unroll
        for (int i = 0; i < 8; i++)
#pragma unroll
            for (int j = 0; j < 4; j++) s[i][j] = 0.f;
        mma_pass2(st, aqh, aql, s, lane);      // (TQh + TQl) . Kh, Kh loaded once
        mma_pass(st + TILE_B, aqh, s, lane);   // TQh . Kl

        // online softmax in exp2 domain (scores scaled by 8*log2 e)
        float rm0 = -INFINITY, rm1 = -INFINITY;
#pragma unroll
        for (int i = 0; i < 8; i++) {
            s[i][0] *= SCALE2; s[i][1] *= SCALE2; s[i][2] *= SCALE2; s[i][3] *= SCALE2;
            rm0 = fmaxf(rm0, fmaxf(s[i][0], s[i][1]));
            rm1 = fmaxf(rm1, fmaxf(s[i][2], s[i][3]));
        }
        rm0 = fmaxf(rm0, __shfl_xor_sync(0xffffffffu, rm0, 1));
        rm0 = fmaxf(rm0, __shfl_xor_sync(0xffffffffu, rm0, 2));
        rm1 = fmaxf(rm1, __shfl_xor_sync(0xffffffffu, rm1, 1));
        rm1 = fmaxf(rm1, __shfl_xor_sync(0xffffffffu, rm1, 2));
        float mn0 = fmaxf(m0, rm0), mn1 = fmaxf(m1, rm1);
        float c0 = ex2f(m0 - mn0), c1 = ex2f(m1 - mn1);
        l0 *= c0; l1 *= c1;
#pragma unroll
        for (int i = 0; i < 8; i++) {
            o[i][0] *= c0; o[i][1] *= c0; o[i][2] *= c1; o[i][3] *= c1;
            float p0 = ex2f(s[i][0] - mn0), p1 = ex2f(s[i][1] - mn0);
            float p2 = ex2f(s[i][2] - mn1), p3 = ex2f(s[i][3] - mn1);
            s[i][0] = p0; s[i][1] = p1; s[i][2] = p2; s[i][3] = p3;
            l0 += p0 + p1; l1 += p2 + p3;
        }
        m0 = mn0; m1 = mn1;

        pv2_pass(st + 2 * TILE_B, s, o, lane);    // (Ph + Pl) . Vh, Vh loaded once
        pv_hi_pass(st + 3 * TILE_B, s, o, lane);  // Ph . Vl
        // no trailing sync: next iteration's top barrier guards stage reuse
    }

    l0 += __shfl_xor_sync(0xffffffffu, l0, 1);
    l0 += __shfl_xor_sync(0xffffffffu, l0, 2);
    l1 += __shfl_xor_sync(0xffffffffu, l1, 1);
    l1 += __shfl_xor_sync(0xffffffffu, l1, 2);
    float inv0 = 1.f / l0, inv1 = 1.f / l1;

    const int row0 = rowBase + wrow + (lane >> 2);
#pragma unroll
    for (int j = 0; j < 8; j++) {
        int col = h * DHEAD + j * 8 + 2 * (lane & 3);
        size_t i0 = (size_t)(b * SEQ + row0) * EMB + col;
        size_t i1 = (size_t)(b * SEQ + row0 + 8) * EMB + col;
        uint32_t hp, lp;
        split2pair(o[j][0] * inv0, o[j][1] * inv0, hp, lp);
        *(uint32_t*)(g_Oh + i0) = hp;
        *(uint32_t*)(g_Ol + i0) = lp;
        split2pair(o[j][2] * inv1, o[j][3] * inv1, hp, lp);
        *(uint32_t*)(g_Oh + i1) = hp;
        *(uint32_t*)(g_Ol + i1) = lp;
    }
}

// ---------------- launch ------------------------------------------------------
extern "C" void kernel_launch(void* const* d_in, const int* in_sizes, int n_in,
                              void* d_out, int out_size)
{
    const float* x     = (const float*)d_in[0];
    const float* tx    = (const float*)d_in[1];
    const float* Wqkv  = (const float*)d_in[2];
    const float* Wtqkv = (const float*)d_in[3];
    const float* Wout  = (const float*)d_in[4];
    float* out = (float*)d_out;

    cudaFuncSetAttribute(gemm_proj3, cudaFuncAttributeMaxDynamicSharedMemorySize, GSMEM);
    cudaFuncSetAttribute(gemm_out,   cudaFuncAttributeMaxDynamicSharedMemorySize, GSMEM);
    cudaFuncSetAttribute(flash_attn, cudaFuncAttributeMaxDynamicSharedMemorySize, FSMEM);

    int tot = CONVQ + PERMN;
    prep_kernel<<<(tot + 255) / 256, 256>>>(x, tx, Wout, Wqkv, Wtqkv);

    gemm_proj3<<<dim3(EMB/128, MROWS/128, 3), 256, GSMEM>>>();

    flash_attn<<<dim3(SEQ/128, NSLICE), 256, FSMEM>>>();

    gemm_out<<<dim3(EMB/128, MROWS/128), 256, GSMEM>>>(out);
}

// round 17
// speedup vs baseline: 1.1260x; 1.0054x over previous
#include <cuda_runtime.h>
#include <cuda_bf16.h>
#include <math.h>
#include <stdint.h>

#define BATCH 2
#define SEQ   2048
#define EMB   1024
#define HEADS 16
#define DHEAD 64
#define MROWS (BATCH*SEQ)         // 4096
#define NSLICE (BATCH*HEADS)      // 32
#define SCALE2 11.5415603271862624f   // 8 * log2(e), folded into TQ

// ---------------- scratch (static device globals; no allocation) -------------
__device__ __nv_bfloat16 g_xh [MROWS*EMB], g_xl [MROWS*EMB];
__device__ __nv_bfloat16 g_txh[MROWS*EMB], g_txl[MROWS*EMB];
__device__ __nv_bfloat16 g_Kh [MROWS*EMB], g_Kl [MROWS*EMB];
__device__ __nv_bfloat16 g_TQh[MROWS*EMB], g_TQl[MROWS*EMB];
__device__ __nv_bfloat16 g_Vth[NSLICE*DHEAD*SEQ], g_Vtl[NSLICE*DHEAD*SEQ];
__device__ __nv_bfloat16 g_Oh [MROWS*EMB], g_Ol [MROWS*EMB];
__device__ __nv_bfloat16 g_Wkh [EMB*EMB], g_Wkl [EMB*EMB];
__device__ __nv_bfloat16 g_Wvh [EMB*EMB], g_Wvl [EMB*EMB];
__device__ __nv_bfloat16 g_Wtqh[EMB*EMB], g_Wtql[EMB*EMB];
__device__ __nv_bfloat16 g_Wouth[EMB*EMB], g_Woutl[EMB*EMB];

// ---------------- small helpers ----------------------------------------------
__device__ __forceinline__ uint32_t smem_u32(const void* p) {
    uint32_t a;
    asm("{ .reg .u64 t; cvta.to.shared.u64 t, %1; cvt.u32.u64 %0, t; }" : "=r"(a) : "l"(p));
    return a;
}
#define CP_ASYNC16(dst, src) \
    asm volatile("cp.async.cg.shared.global [%0], [%1], 16;" :: "r"(dst), "l"(src) : "memory")
#define CP_COMMIT() asm volatile("cp.async.commit_group;" ::: "memory")
#define CP_WAIT2()  asm volatile("cp.async.wait_group 2;" ::: "memory")
#define CP_WAIT1()  asm volatile("cp.async.wait_group 1;" ::: "memory")
#define CP_WAIT0()  asm volatile("cp.async.wait_group 0;" ::: "memory")

__device__ __forceinline__ void ldsm_x4(uint32_t r[4], uint32_t addr) {
    asm volatile("ldmatrix.sync.aligned.m8n8.x4.shared.b16 {%0,%1,%2,%3}, [%4];"
                 : "=r"(r[0]), "=r"(r[1]), "=r"(r[2]), "=r"(r[3]) : "r"(addr));
}
__device__ __forceinline__ void mma16816(float c[4], const uint32_t a[4],
                                         uint32_t b0, uint32_t b1) {
    asm volatile("mma.sync.aligned.m16n8k16.row.col.f32.bf16.bf16.f32 "
                 "{%0,%1,%2,%3},{%4,%5,%6,%7},{%8,%9},{%0,%1,%2,%3};"
                 : "+f"(c[0]), "+f"(c[1]), "+f"(c[2]), "+f"(c[3])
                 : "r"(a[0]), "r"(a[1]), "r"(a[2]), "r"(a[3]), "r"(b0), "r"(b1));
}
__device__ __forceinline__ uint32_t pack2(__nv_bfloat16 a, __nv_bfloat16 b) {
    return (uint32_t)__bfloat16_as_ushort(a) | ((uint32_t)__bfloat16_as_ushort(b) << 16);
}
__device__ __forceinline__ void split2(float x, __nv_bfloat16& h, __nv_bfloat16& l) {
    h = __float2bfloat16(x);
    l = __float2bfloat16(x - __bfloat162float(h));
}
__device__ __forceinline__ uint32_t cvt2(float x0, float x1) {
    uint32_t r;
    asm("cvt.rn.bf16x2.f32 %0, %1, %2;" : "=r"(r) : "f"(x1), "f"(x0));
    return r;
}
__device__ __forceinline__ void split2pair(float x0, float x1,
                                           uint32_t& hp, uint32_t& lp) {
    hp = cvt2(x0, x1);
    float h0 = __uint_as_float(hp << 16);
    float h1 = __uint_as_float(hp & 0xffff0000u);
    lp = cvt2(x0 - h0, x1 - h1);
}
__device__ __forceinline__ float ex2f(float x) {
    float r;
    asm("ex2.approx.ftz.f32 %0, %1;" : "=f"(r) : "f"(x));
    return r;
}

// smem tile geometry
#define SSTR 80              // 32-half rows (projection GEMMs)
#define TB   (128*SSTR)      // 10240 (one 128x32 operand tile)
#define SSTR64 144           // 64-half rows (flash kernel), conflict-free
#define TILE_B (64*SSTR64)   // 9216

__device__ __forceinline__ void fill_rows(uint32_t dst, const __nv_bfloat16* src,
                                          int ld, int rows, int tid) {
    for (int j = tid; j < rows * 4; j += 256) {
        int r = j >> 2, cc = j & 3;
        CP_ASYNC16(dst + r * SSTR + cc * 16, src + (size_t)r * ld + cc * 8);
    }
}

// ---------------- prep: convert x/tx/Wout + permute/split Wqkv,Wtqkv ---------
#define NQ ((MROWS*EMB)/4)       // 1048576
#define WQ ((EMB*EMB)/4)         // 262144
#define CONVQ (2*NQ + WQ)        // 2359296
#define PERMN (EMB*EMB)          // 1048576

__global__ void prep_kernel(const float* __restrict__ X0, const float* __restrict__ X1,
                            const float* __restrict__ X2,
                            const float* __restrict__ Wqkv, const float* __restrict__ Wtqkv)
{
    int i = blockIdx.x * blockDim.x + threadIdx.x;
    if (i < CONVQ) {
        const float* X; __nv_bfloat16 *H, *L;
        if (i < NQ)          { X = X0; H = g_xh;  L = g_xl; }
        else if (i < 2 * NQ) { X = X1; H = g_txh; L = g_txl; i -= NQ; }
        else                 { X = X2; H = g_Wouth; L = g_Woutl; i -= 2 * NQ; }
        float4 v = ((const float4*)X)[i];
        uint32_t h01, l01, h23, l23;
        split2pair(v.x, v.y, h01, l01);
        split2pair(v.z, v.w, h23, l23);
        ((uint2*)H)[i] = make_uint2(h01, h23);
        ((uint2*)L)[i] = make_uint2(l01, l23);
        return;
    }
    i -= CONVQ;
    if (i >= PERMN) return;
    int k = i & 1023, n = i >> 10;
    int h = n >> 6, d = n & 63;
    size_t dst = (size_t)n * EMB + k;
    float vk  = Wqkv [(size_t)(d * 48 + 16 + h) * EMB + k];
    float vv  = Wqkv [(size_t)(d * 48 + 32 + h) * EMB + k];
    float vtq = Wtqkv[(size_t)(d * 48 +  0 + h) * EMB + k];
    __nv_bfloat16 hh, ll;
    split2(vk,  hh, ll); g_Wkh [dst] = hh; g_Wkl [dst] = ll;
    split2(vv,  hh, ll); g_Wvh [dst] = hh; g_Wvl [dst] = ll;
    split2(vtq, hh, ll); g_Wtqh[dst] = hh; g_Wtql[dst] = ll;
}

// ---------------- GEMM core: fused 3-term k-slices, 2 stages (occ 2) ---------
#define KCH  32
#define STG  (4*TB)        // 40960
#define GSMEM (2*STG)      // 81920

__device__ __forceinline__ void fill_all(uint32_t st,
    const __nv_bfloat16* Ah, const __nv_bfloat16* Al,
    const __nv_bfloat16* Bh, const __nv_bfloat16* Bl,
    int rowBase, int colBase, int k0, int tid)
{
    fill_rows(st,          Ah + (size_t)rowBase * EMB + k0, EMB, 128, tid);
    fill_rows(st + TB,     Al + (size_t)rowBase * EMB + k0, EMB, 128, tid);
    fill_rows(st + 2 * TB, Bh + (size_t)colBase * EMB + k0, EMB, 128, tid);
    fill_rows(st + 3 * TB, Bl + (size_t)colBase * EMB + k0, EMB, 128, tid);
}

__device__ __forceinline__ void compute_all(uint32_t st, int wrow, int wcol,
                                            int lane, float (*cfr)[4])
{
    const int arow  = wrow + (lane & 15);
    const int acolh = (lane >> 4) * 8;
    const int brow  = wcol + (lane & 7) + ((lane >> 4) << 3);
    const int bcolh = ((lane >> 3) & 1) * 8;
#pragma unroll
    for (int ks = 0; ks < 2; ks++) {
        uint32_t ah[4][4], al[4][4], bh[2][4], bl[2][4];
#pragma unroll
        for (int mt = 0; mt < 4; mt++) {
            uint32_t off = (uint32_t)(arow + mt * 16) * SSTR + (acolh + ks * 16) * 2;
            ldsm_x4(ah[mt], st + off);
            ldsm_x4(al[mt], st + TB + off);
        }
#pragma unroll
        for (int np = 0; np < 2; np++) {
            uint32_t off = (uint32_t)(brow + np * 16) * SSTR + (bcolh + ks * 16) * 2;
            ldsm_x4(bh[np], st + 2 * TB + off);
            ldsm_x4(bl[np], st + 3 * TB + off);
        }
#pragma unroll
        for (int mt = 0; mt < 4; mt++)
#pragma unroll
            for (int np = 0; np < 2; np++) {
                mma16816(cfr[(mt * 2 + np) * 2 + 0], ah[mt], bh[np][0], bh[np][1]);
                mma16816(cfr[(mt * 2 + np) * 2 + 1], ah[mt], bh[np][2], bh[np][3]);
            }
#pragma unroll
        for (int mt = 0; mt < 4; mt++)
#pragma unroll
            for (int np = 0; np < 2; np++) {
                mma16816(cfr[(mt * 2 + np) * 2 + 0], al[mt], bh[np][0], bh[np][1]);
                mma16816(cfr[(mt * 2 + np) * 2 + 1], al[mt], bh[np][2], bh[np][3]);
            }
#pragma unroll
        for (int mt = 0; mt < 4; mt++)
#pragma unroll
            for (int np = 0; np < 2; np++) {
                mma16816(cfr[(mt * 2 + np) * 2 + 0], ah[mt], bl[np][0], bl[np][1]);
                mma16816(cfr[(mt * 2 + np) * 2 + 1], ah[mt], bl[np][2], bl[np][3]);
            }
    }
}

__device__ __forceinline__ void gemm_core(
    const __nv_bfloat16* Ah, const __nv_bfloat16* Al,
    const __nv_bfloat16* Bh, const __nv_bfloat16* Bl,
    int rowBase, int colBase, uint32_t sb, int tid, int lane,
    int wrow, int wcol, float (*cfr)[4])
{
    fill_all(sb,       Ah, Al, Bh, Bl, rowBase, colBase, 0,  tid); CP_COMMIT();
    fill_all(sb + STG, Ah, Al, Bh, Bl, rowBase, colBase, 32, tid); CP_COMMIT();
    for (int c = 0; c < KCH; c++) {
        if (c + 1 < KCH) CP_WAIT1(); else CP_WAIT0();
        __syncthreads();
        uint32_t st = sb + (c & 1) * STG;
        compute_all(st, wrow, wcol, lane, cfr);
        __syncthreads();
        if (c + 2 < KCH) {
            fill_all(st, Ah, Al, Bh, Bl, rowBase, colBase, (c + 2) << 5, tid);
            CP_COMMIT();
        }
    }
}

// ---------------- merged projection GEMM (z: 0=K split, 1=V->Vt, 2=TQ split) -
__global__ void __launch_bounds__(256, 2)
gemm_proj3()
{
    extern __shared__ char smem[];
    uint32_t sb = smem_u32(smem);
    const int tid = threadIdx.x, lane = tid & 31, warp = tid >> 5;
    const int rowBase = blockIdx.y * 128, colBase = blockIdx.x * 128;
    const int z = blockIdx.z;
    const int wrow = (warp >> 2) * 64, wcol = (warp & 3) * 32;

    const __nv_bfloat16 *Ah, *Al, *Bh, *Bl;
    if (z == 0)      { Ah = g_xh;  Al = g_xl;  Bh = g_Wkh;  Bl = g_Wkl;  }
    else if (z == 1) { Ah = g_xh;  Al = g_xl;  Bh = g_Wvh;  Bl = g_Wvl;  }
    else             { Ah = g_txh; Al = g_txl; Bh = g_Wtqh; Bl = g_Wtql; }

    float cfr[16][4];
#pragma unroll
    for (int i = 0; i < 16; i++)
#pragma unroll
        for (int j = 0; j < 4; j++) cfr[i][j] = 0.f;

    gemm_core(Ah, Al, Bh, Bl, rowBase, colBase, sb, tid, lane, wrow, wcol, cfr);

    if (z != 1) {
        // TQ (z==2) gets the softmax scale folded in before split
        const float sc = (z == 2) ? SCALE2 : 1.0f;
        __nv_bfloat16* H = (z == 0) ? g_Kh : g_TQh;
        __nv_bfloat16* L = (z == 0) ? g_Kl : g_TQl;
#pragma unroll
        for (int mt = 0; mt < 4; mt++)
#pragma unroll
            for (int np = 0; np < 2; np++)
#pragma unroll
                for (int t8 = 0; t8 < 2; t8++) {
                    int nt = np * 2 + t8;
                    int row = rowBase + wrow + mt * 16 + (lane >> 2);
                    int col = colBase + wcol + nt * 8 + 2 * (lane & 3);
                    float* cc = cfr[(mt * 2 + np) * 2 + t8];
#pragma unroll
                    for (int half = 0; half < 2; half++) {
                        int r = row + half * 8;
                        uint32_t hp, lp;
                        split2pair(cc[half * 2] * sc, cc[half * 2 + 1] * sc, hp, lp);
                        *(uint32_t*)(H + (size_t)r * EMB + col) = hp;
                        *(uint32_t*)(L + (size_t)r * EMB + col) = lp;
                    }
                }
    } else {
        // V: transpose in smem, write Vt[z][d][t] split bf16, t-coalesced
        CP_WAIT0();
        __syncthreads();
        float* tile = (float*)smem;   // [col][row], pitch 129: 66048 B <= 81920
#pragma unroll
        for (int mt = 0; mt < 4; mt++)
#pragma unroll
            for (int np = 0; np < 2; np++)
#pragma unroll
                for (int t8 = 0; t8 < 2; t8++) {
                    int nt = np * 2 + t8;
                    int rl = wrow + mt * 16 + (lane >> 2);
                    int cl = wcol + nt * 8 + 2 * (lane & 3);
                    float* cc = cfr[(mt * 2 + np) * 2 + t8];
#pragma unroll
                    for (int half = 0; half < 2; half++) {
                        tile[(cl + 0) * 129 + rl + half * 8] = cc[half * 2];
                        tile[(cl + 1) * 129 + rl + half * 8] = cc[half * 2 + 1];
                    }
                }
        __syncthreads();
        const int bb = rowBase >> 11, t0 = rowBase & 2047;
        for (int j = tid; j < 128 * 16; j += 256) {
            int c = j >> 4, tc = j & 15;
            int dg = colBase + c, hh = dg >> 6, dd = dg & 63;
            size_t dst = (((size_t)(bb * 16 + hh)) * DHEAD + dd) * SEQ + t0 + tc * 8;
            uint32_t hv[4], lv[4];
#pragma unroll
            for (int u = 0; u < 4; u++) {
                float v0 = tile[c * 129 + tc * 8 + 2 * u];
                float v1 = tile[c * 129 + tc * 8 + 2 * u + 1];
                split2pair(v0, v1, hv[u], lv[u]);
            }
            *(uint4*)(g_Vth + dst) = make_uint4(hv[0], hv[1], hv[2], hv[3]);
            *(uint4*)(g_Vtl + dst) = make_uint4(lv[0], lv[1], lv[2], lv[3]);
        }
    }
}

// ---------------- output GEMM (fp32 out) -------------------------------------
__global__ void __launch_bounds__(256, 2)
gemm_out(float* __restrict__ C)
{
    extern __shared__ char smem[];
    uint32_t sb = smem_u32(smem);
    const int tid = threadIdx.x, lane = tid & 31, warp = tid >> 5;
    const int rowBase = blockIdx.y * 128, colBase = blockIdx.x * 128;
    const int wrow = (warp >> 2) * 64, wcol = (warp & 3) * 32;

    float cfr[16][4];
#pragma unroll
    for (int i = 0; i < 16; i++)
#pragma unroll
        for (int j = 0; j < 4; j++) cfr[i][j] = 0.f;

    gemm_core(g_Oh, g_Ol, g_Wouth, g_Woutl, rowBase, colBase, sb, tid, lane, wrow, wcol, cfr);

#pragma unroll
    for (int mt = 0; mt < 4; mt++)
#pragma unroll
        for (int np = 0; np < 2; np++)
#pragma unroll
            for (int t8 = 0; t8 < 2; t8++) {
                int nt = np * 2 + t8;
                int row = rowBase + wrow + mt * 16 + (lane >> 2);
                int col = colBase + wcol + nt * 8 + 2 * (lane & 3);
                float* cc = cfr[(mt * 2 + np) * 2 + t8];
#pragma unroll
                for (int half = 0; half < 2; half++) {
                    int r = row + half * 8;
                    *(float2*)(C + (size_t)r * EMB + col) =
                        make_float2(cc[half * 2], cc[half * 2 + 1]);
                }
            }
}

// ---------------- fused flash attention (HMMA, 3-term split, 3-stage) --------
#define FSTAGE (4*TILE_B)    // 36864
#define FSMEM  (3*FSTAGE)    // 110592
#define NT     (SEQ/64)      // 32

__device__ __forceinline__ void fill_kv(uint32_t st, int t, int b, int h, int z, int tid)
{
    const size_t koff = (size_t)(b * SEQ + t * 64) * EMB + h * DHEAD;
    const size_t voff = (size_t)z * DHEAD * SEQ + t * 64;
    for (int j = tid; j < 64 * 8; j += 256) {
        int r = j >> 3, c = j & 7;
        uint32_t d = (uint32_t)r * SSTR64 + c * 16;
        size_t ko = koff + (size_t)r * EMB + c * 8;
        size_t vo = voff + (size_t)r * SEQ + c * 8;
        CP_ASYNC16(st + d,              g_Kh  + ko);
        CP_ASYNC16(st + TILE_B + d,     g_Kl  + ko);
        CP_ASYNC16(st + 2 * TILE_B + d, g_Vth + vo);
        CP_ASYNC16(st + 3 * TILE_B + d, g_Vtl + vo);
    }
}

__device__ __forceinline__ void mma_pass(uint32_t bbase, const uint32_t A[4][4],
                                         float (*s)[4], int lane)
{
    const int brow  = (lane & 7) + ((lane >> 4) << 3);
    const int bcolh = ((lane >> 3) & 1) * 8;
#pragma unroll
    for (int ks = 0; ks < 4; ks++) {
#pragma unroll
        for (int pr = 0; pr < 4; pr++) {
            uint32_t bf[4];
            ldsm_x4(bf, bbase + (uint32_t)(brow + pr * 16) * SSTR64 + (bcolh + ks * 16) * 2);
            mma16816(s[pr * 2 + 0], A[ks], bf[0], bf[1]);
            mma16816(s[pr * 2 + 1], A[ks], bf[2], bf[3]);
        }
    }
}

__device__ __forceinline__ void mma_pass2(uint32_t bbase, const uint32_t A1[4][4],
                                          const uint32_t A2[4][4],
                                          float (*s)[4], int lane)
{
    const int brow  = (lane & 7) + ((lane >> 4) << 3);
    const int bcolh = ((lane >> 3) & 1) * 8;
#pragma unroll
    for (int ks = 0; ks < 4; ks++) {
#pragma unroll
        for (int pr = 0; pr < 4; pr++) {
            uint32_t bf[4];
            ldsm_x4(bf, bbase + (uint32_t)(brow + pr * 16) * SSTR64 + (bcolh + ks * 16) * 2);
            mma16816(s[pr * 2 + 0], A1[ks], bf[0], bf[1]);
            mma16816(s[pr * 2 + 1], A1[ks], bf[2], bf[3]);
            mma16816(s[pr * 2 + 0], A2[ks], bf[0], bf[1]);
            mma16816(s[pr * 2 + 1], A2[ks], bf[2], bf[3]);
        }
    }
}

__device__ __forceinline__ void pv2_pass(uint32_t bbase, const float (*s)[4],
                                         float (*o)[4], int lane)
{
    const int brow  = (lane & 7) + ((lane >> 4) << 3);
    const int bcolh = ((lane >> 3) & 1) * 8;
#pragma unroll
    for (int ks = 0; ks < 4; ks++) {
        const float* c0 = s[2 * ks];
        const float* c1 = s[2 * ks + 1];
        uint32_t Ah[4], Al[4];
        split2pair(c0[0], c0[1], Ah[0], Al[0]);
        split2pair(c0[2], c0[3], Ah[1], Al[1]);
        split2pair(c1[0], c1[1], Ah[2], Al[2]);
        split2pair(c1[2], c1[3], Ah[3], Al[3]);
#pragma unroll
        for (int pr = 0; pr < 4; pr++) {
            uint32_t bf[4];
            ldsm_x4(bf, bbase + (uint32_t)(brow + pr * 16) * SSTR64 + (bcolh + ks * 16) * 2);
            mma16816(o[pr * 2 + 0], Ah, bf[0], bf[1]);
            mma16816(o[pr * 2 + 1], Ah, bf[2], bf[3]);
            mma16816(o[pr * 2 + 0], Al, bf[0], bf[1]);
            mma16816(o[pr * 2 + 1], Al, bf[2], bf[3]);
        }
    }
}

__device__ __forceinline__ void pv_hi_pass(uint32_t bbase, const float (*s)[4],
                                           float (*o)[4], int lane)
{
    const int brow  = (lane & 7) + ((lane >> 4) << 3);
    const int bcolh = ((lane >> 3) & 1) * 8;
#pragma unroll
    for (int ks = 0; ks < 4; ks++) {
        const float* c0 = s[2 * ks];
        const float* c1 = s[2 * ks + 1];
        uint32_t Ah[4];
        Ah[0] = cvt2(c0[0], c0[1]);
        Ah[1] = cvt2(c0[2], c0[3]);
        Ah[2] = cvt2(c1[0], c1[1]);
        Ah[3] = cvt2(c1[2], c1[3]);
#pragma unroll
        for (int pr = 0; pr < 4; pr++) {
            uint32_t bf[4];
            ldsm_x4(bf, bbase + (uint32_t)(brow + pr * 16) * SSTR64 + (bcolh + ks * 16) * 2);
            mma16816(o[pr * 2 + 0], Ah, bf[0], bf[1]);
            mma16816(o[pr * 2 + 1], Ah, bf[2], bf[3]);
        }
    }
}

__global__ void __launch_bounds__(256, 2)
flash_attn()
{
    extern __shared__ char smem[];
    uint32_t sb = smem_u32(smem);
    const int tid = threadIdx.x, lane = tid & 31, warp = tid >> 5;
    const int rowBase = blockIdx.x * 128;
    const int z = blockIdx.y, b = z >> 4, h = z & 15;
    const int wrow = warp * 16;
    const int arow  = wrow + (lane & 15);
    const int acolh = (lane >> 4) * 8;

    // stage TQ (hi into stage0 low half, lo into stage0 high half)
    {
        const size_t toff = (size_t)(b * SEQ + rowBase) * EMB + h * DHEAD;
        for (int j = tid; j < 128 * 8; j += 256) {
            int r = j >> 3, c = j & 7;
            uint32_t d = (uint32_t)r * SSTR64 + c * 16;
            size_t go = toff + (size_t)r * EMB + c * 8;
            CP_ASYNC16(sb + d,         g_TQh + go);
            CP_ASYNC16(sb + 18432 + d, g_TQl + go);
        }
        CP_COMMIT(); CP_WAIT0();
    }
    __syncthreads();

    uint32_t aqh[4][4], aql[4][4];
#pragma unroll
    for (int ks = 0; ks < 4; ks++) {
        ldsm_x4(aqh[ks], sb + (uint32_t)arow * SSTR64 + (acolh + ks * 16) * 2);
        ldsm_x4(aql[ks], sb + 18432 + (uint32_t)arow * SSTR64 + (acolh + ks * 16) * 2);
    }
    __syncthreads();   // stage0 free for K/V

    float o[8][4];
#pragma unroll
    for (int i = 0; i < 8; i++)
#pragma unroll
        for (int j = 0; j < 4; j++) o[i][j] = 0.f;
    float m0 = -INFINITY, m1 = -INFINITY, l0 = 0.f, l1 = 0.f;

    fill_kv(sb, 0, b, h, z, tid);           CP_COMMIT();
    fill_kv(sb + FSTAGE, 1, b, h, z, tid);  CP_COMMIT();

    uint32_t stv[3] = {sb, sb + FSTAGE, sb + 2 * FSTAGE};
    for (int t = 0; t < NT; t++) {
        if (t + 1 < NT) { CP_WAIT1(); } else { CP_WAIT0(); }
        __syncthreads();   // all warps done with stage (t-1)%3 before refill
        if (t + 2 < NT) {
            fill_kv(stv[(t + 2) % 3], t + 2, b, h, z, tid);
            CP_COMMIT();
        }
        uint32_t st = stv[t % 3];

        float s[8][4];
#pragma unroll
        for (int i = 0; i < 8; i++)
#pragma unroll
            for (int j = 0; j < 4; j++) s[i][j] = 0.f;
        mma_pass2(st, aqh, aql, s, lane);      // (TQh + TQl) . Kh  (TQ pre-scaled)

        // approximate row max from 2-term partial S (m cancels exactly in the
        // softmax quotient; partial max is within ~eps of true max, safe for
        // range control). Overlaps with the Kl MMA pass below.
        float rm0 = -INFINITY, rm1 = -INFINITY;
#pragma unroll
        for (int i = 0; i < 8; i++) {
            rm0 = fmaxf(rm0, fmaxf(s[i][0], s[i][1]));
            rm1 = fmaxf(rm1, fmaxf(s[i][2], s[i][3]));
        }
        rm0 = fmaxf(rm0, __shfl_xor_sync(0xffffffffu, rm0, 1));
        rm0 = fmaxf(rm0, __shfl_xor_sync(0xffffffffu, rm0, 2));
        rm1 = fmaxf(rm1, __shfl_xor_sync(0xffffffffu, rm1, 1));
        rm1 = fmaxf(rm1, __shfl_xor_sync(0xffffffffu, rm1, 2));

        mma_pass(st + TILE_B, aqh, s, lane);   // TQh . Kl (third split term)

        float mn0 = fmaxf(m0, rm0), mn1 = fmaxf(m1, rm1);
        float c0 = ex2f(m0 - mn0), c1 = ex2f(m1 - mn1);
        l0 *= c0; l1 *= c1;
#pragma unroll
        for (int i = 0; i < 8; i++) {
            o[i][0] *= c0; o[i][1] *= c0; o[i][2] *= c1; o[i][3] *= c1;
            float p0 = ex2f(s[i][0] - mn0), p1 = ex2f(s[i][1] - mn0);
            float p2 = ex2f(s[i][2] - mn1), p3 = ex2f(s[i][3] - mn1);
            s[i][0] = p0; s[i][1] = p1; s[i][2] = p2; s[i][3] = p3;
            l0 += p0 + p1; l1 += p2 + p3;
        }
        m0 = mn0; m1 = mn1;

        pv2_pass(st + 2 * TILE_B, s, o, lane);    // (Ph + Pl) . Vh, Vh loaded once
        pv_hi_pass(st + 3 * TILE_B, s, o, lane);  // Ph . Vl
        // no trailing sync: next iteration's top barrier guards stage reuse
    }

    l0 += __shfl_xor_sync(0xffffffffu, l0, 1);
    l0 += __shfl_xor_sync(0xffffffffu, l0, 2);
    l1 += __shfl_xor_sync(0xffffffffu, l1, 1);
    l1 += __shfl_xor_sync(0xffffffffu, l1, 2);
    float inv0 = 1.f / l0, inv1 = 1.f / l1;

    const int row0 = rowBase + wrow + (lane >> 2);
#pragma unroll
    for (int j = 0; j < 8; j++) {
        int col = h * DHEAD + j * 8 + 2 * (lane & 3);
        size_t i0 = (size_t)(b * SEQ + row0) * EMB + col;
        size_t i1 = (size_t)(b * SEQ + row0 + 8) * EMB + col;
        uint32_t hp, lp;
        split2pair(o[j][0] * inv0, o[j][1] * inv0, hp, lp);
        *(uint32_t*)(g_Oh + i0) = hp;
        *(uint32_t*)(g_Ol + i0) = lp;
        split2pair(o[j][2] * inv1, o[j][3] * inv1, hp, lp);
        *(uint32_t*)(g_Oh + i1) = hp;
        *(uint32_t*)(g_Ol + i1) = lp;
    }
}

// ---------------- launch ------------------------------------------------------
extern "C" void kernel_launch(void* const* d_in, const int* in_sizes, int n_in,
                              void* d_out, int out_size)
{
    const float* x     = (const float*)d_in[0];
    const float* tx    = (const float*)d_in[1];
    const float* Wqkv  = (const float*)d_in[2];
    const float* Wtqkv = (const float*)d_in[3];
    const float* Wout  = (const float*)d_in[4];
    float* out = (float*)d_out;

    cudaFuncSetAttribute(gemm_proj3, cudaFuncAttributeMaxDynamicSharedMemorySize, GSMEM);
    cudaFuncSetAttribute(gemm_out,   cudaFuncAttributeMaxDynamicSharedMemorySize, GSMEM);
    cudaFuncSetAttribute(flash_attn, cudaFuncAttributeMaxDynamicSharedMemorySize, FSMEM);

    int tot = CONVQ + PERMN;
    prep_kernel<<<(tot + 255) / 256, 256>>>(x, tx, Wout, Wqkv, Wtqkv);

    gemm_proj3<<<dim3(EMB/128, MROWS/128, 3), 256, GSMEM>>>();

    flash_attn<<<dim3(SEQ/128, NSLICE), 256, FSMEM>>>();

    gemm_out<<<dim3(EMB/128, MROWS/128), 256, GSMEM>>>(out);
}